// round 5
// baseline (speedup 1.0000x reference)
#include <cuda_runtime.h>

#define BB   8
#define SS   1024
#define DD   768
#define HH   8
#define DKK  96
#define FFD  1024
#define NR   (BB * SS)        // 8192 rows
#define NBH  (BB * HH)        // 64 (b,h) pairs

// ---------------- scratch (static device globals; no allocation) ----------------
__device__ float g_q [NR * DD];
__device__ float g_kv[NR * DD];
__device__ float g_w [(size_t)NBH * SS * SS];   // 268 MB score matrix
__device__ float g_cm[NBH * SS];
__device__ float g_cs[NBH * SS];
__device__ float g_o [NR * DD];
__device__ float g_x1[NR * DD];
__device__ float g_x2[NR * DD];
__device__ float g_h [NR * FFD];
__device__ unsigned char g_mask[NR];   // canonical per-(b,q) pad mask, 0/1
__device__ int g_flags[2];             // [0]=any byte >1, [1]=any misaligned byte nonzero

// ---------------- mask dtype detection + canonicalization ------------------------
// The reference mask is bool; the harness may deliver it as uint8, int32 or float32.
// Scan only the first NR bytes (valid under every interpretation):
//   any byte > 1                       -> 32-bit float words
//   else any nonzero byte at i%4 != 0  -> true uint8 layout
//   else                               -> 32-bit int words (0/1)
// "nonzero 32-bit word" is the correct truth test for both int32 and float32.
__global__ void detect_mask_kernel(const unsigned char* __restrict__ m)
{
    __shared__ int s_big, s_mis;
    if (threadIdx.x == 0) { s_big = 0; s_mis = 0; }
    __syncthreads();
    int big = 0, mis = 0;
    for (int i = threadIdx.x; i < NR; i += blockDim.x) {
        unsigned char v = m[i];
        if (v > 1) big = 1;
        if ((i & 3) != 0 && v != 0) mis = 1;
    }
    if (big) atomicOr(&s_big, 1);
    if (mis) atomicOr(&s_mis, 1);
    __syncthreads();
    if (threadIdx.x == 0) { g_flags[0] = s_big; g_flags[1] = s_mis; }
}

__global__ void convert_mask_kernel(const void* __restrict__ m)
{
    int i = blockIdx.x * blockDim.x + threadIdx.x;
    bool word32 = (g_flags[0] != 0) || (g_flags[1] == 0);
    unsigned char out;
    if (word32) {
        out = (((const unsigned int*)m)[i] != 0u) ? 1 : 0;
    } else {
        out = (((const unsigned char*)m)[i] != 0) ? 1 : 0;
    }
    g_mask[i] = out;
}

// ---------------- dense GEMM: C = A(MxK) @ W(KxN) + bias, optional relu ----------
// BM=128, BN=128, BK=16, 256 threads, 8x8 microtile (split 4+4 for conflict-free LDS.128)
template <bool RELU>
__global__ __launch_bounds__(256, 2)
void sgemm_bias(const float* __restrict__ A, const float* __restrict__ W,
                const float* __restrict__ bias, float* __restrict__ C,
                int M, int N, int K)
{
    __shared__ float As[16][132];   // transposed A tile, padded
    __shared__ float Bs[16][128];

    const int tid  = threadIdx.x;
    const int tx   = tid & 15;
    const int ty   = tid >> 4;
    const int row0 = blockIdx.y * 128;
    const int col0 = blockIdx.x * 128;

    const int ar = tid >> 2;          // 0..63
    const int ak = (tid & 3) << 2;    // 0,4,8,12
    const int br = tid >> 5;          // 0..7
    const int bc = (tid & 31) << 2;   // 0..124

    float acc[8][8];
#pragma unroll
    for (int i = 0; i < 8; i++)
#pragma unroll
        for (int j = 0; j < 8; j++) acc[i][j] = 0.f;

    for (int k0 = 0; k0 < K; k0 += 16) {
#pragma unroll
        for (int rr = 0; rr < 2; rr++) {
            int r = ar + rr * 64;
            float4 v = *(const float4*)(A + (size_t)(row0 + r) * K + k0 + ak);
            As[ak + 0][r] = v.x;
            As[ak + 1][r] = v.y;
            As[ak + 2][r] = v.z;
            As[ak + 3][r] = v.w;
        }
#pragma unroll
        for (int rr = 0; rr < 2; rr++) {
            int r = br + rr * 8;
            *(float4*)(&Bs[r][bc]) = *(const float4*)(W + (size_t)(k0 + r) * N + col0 + bc);
        }
        __syncthreads();
#pragma unroll
        for (int kk = 0; kk < 16; kk++) {
            float a[8], b[8];
            *(float4*)(&a[0]) = *(const float4*)(&As[kk][ty << 2]);
            *(float4*)(&a[4]) = *(const float4*)(&As[kk][64 + (ty << 2)]);
            *(float4*)(&b[0]) = *(const float4*)(&Bs[kk][tx << 2]);
            *(float4*)(&b[4]) = *(const float4*)(&Bs[kk][64 + (tx << 2)]);
#pragma unroll
            for (int i = 0; i < 8; i++)
#pragma unroll
                for (int j = 0; j < 8; j++)
                    acc[i][j] += a[i] * b[j];
        }
        __syncthreads();
    }

#pragma unroll
    for (int i = 0; i < 8; i++) {
        int r = row0 + ((i < 4) ? ((ty << 2) + i) : (64 + (ty << 2) + (i - 4)));
#pragma unroll
        for (int jh = 0; jh < 2; jh++) {
            int c = col0 + jh * 64 + (tx << 2);
            float4 o;
            o.x = acc[i][jh * 4 + 0] + bias[c + 0];
            o.y = acc[i][jh * 4 + 1] + bias[c + 1];
            o.z = acc[i][jh * 4 + 2] + bias[c + 2];
            o.w = acc[i][jh * 4 + 3] + bias[c + 3];
            if (RELU) {
                o.x = fmaxf(o.x, 0.f); o.y = fmaxf(o.y, 0.f);
                o.z = fmaxf(o.z, 0.f); o.w = fmaxf(o.w, 0.f);
            }
            *(float4*)(C + (size_t)r * N + c) = o;
        }
    }
}

// ---------------- scores: w[bh,q,k] = (q_bh[q,:].kv_bh[k,:])/sqrt(96), masked ----
// grid (S/64 ktiles, S/64 qtiles, BH), 256 threads, 64x64 tile, 4x4 microtile
__global__ __launch_bounds__(256)
void scores_kernel(const float* __restrict__ q, const float* __restrict__ kv,
                   float* __restrict__ w)
{
    const int bh = blockIdx.z;
    const int b  = bh >> 3, h = bh & 7;
    const int k0 = blockIdx.x << 6;
    const int q0 = blockIdx.y << 6;
    const int tid = threadIdx.x;
    const int tx = tid & 15, ty = tid >> 4;

    float* wrow = w + (size_t)bh * SS * SS;

    if (k0 > q0 + 63) {
        // entire tile causally masked -> write -1e9 (needed by column softmax)
        const float4 neg = make_float4(-1e9f, -1e9f, -1e9f, -1e9f);
#pragma unroll
        for (int i = 0; i < 4; i++) {
            int qi = q0 + (ty << 2) + i;
            *(float4*)(wrow + (size_t)qi * SS + k0 + (tx << 2)) = neg;
        }
        return;
    }

    __shared__ float Qs[32][68];
    __shared__ float Ks[32][68];

    float acc[4][4];
#pragma unroll
    for (int i = 0; i < 4; i++)
#pragma unroll
        for (int j = 0; j < 4; j++) acc[i][j] = 0.f;

    const float* qb = q  + (size_t)(b * SS + q0) * DD + h * DKK;
    const float* kb = kv + (size_t)(b * SS + k0) * DD + h * DKK;

    for (int c = 0; c < 3; c++) {        // DK=96 in 3 chunks of 32
#pragma unroll
        for (int it = 0; it < 8; it++) {
            int idx = tid + (it << 8);
            int r = idx >> 5, d = idx & 31;
            Qs[d][r] = qb[(size_t)r * DD + c * 32 + d];
            Ks[d][r] = kb[(size_t)r * DD + c * 32 + d];
        }
        __syncthreads();
#pragma unroll
        for (int kk = 0; kk < 32; kk++) {
            float a[4], bb[4];
            *(float4*)(&a[0])  = *(const float4*)(&Qs[kk][ty << 2]);
            *(float4*)(&bb[0]) = *(const float4*)(&Ks[kk][tx << 2]);
#pragma unroll
            for (int i = 0; i < 4; i++)
#pragma unroll
                for (int j = 0; j < 4; j++)
                    acc[i][j] += a[i] * bb[j];
        }
        __syncthreads();
    }

    const float scale = 0.10206207261596577f;  // 1/sqrt(96)
#pragma unroll
    for (int i = 0; i < 4; i++) {
        int qi = q0 + (ty << 2) + i;
        bool pm = (g_mask[b * SS + qi] != 0);
        float vv[4];
#pragma unroll
        for (int j = 0; j < 4; j++) {
            int ki = k0 + (tx << 2) + j;
            float v = acc[i][j] * scale;
            if (pm || ki > qi) v = -1e9f;
            vv[j] = v;
        }
        float4 o = make_float4(vv[0], vv[1], vv[2], vv[3]);
        *(float4*)(wrow + (size_t)qi * SS + k0 + (tx << 2)) = o;
    }
}

// ---------------- column softmax stats: per (bh, k), max & sum over q ------------
__global__ __launch_bounds__(256)
void colstats_kernel(const float* __restrict__ w, float* __restrict__ cm,
                     float* __restrict__ cs)
{
    const int bh = blockIdx.y;
    const int k  = (blockIdx.x << 8) + threadIdx.x;
    const float* wb = w + (size_t)bh * SS * SS + k;
    float m = __int_as_float(0xff800000);  // -inf
    float s = 0.f;
    for (int qq = 0; qq < SS; qq++) {
        float v = wb[(size_t)qq * SS];
        if (v > m) {
            s = s * __expf(m - v) + 1.0f;
            m = v;
        } else {
            s += __expf(v - m);
        }
    }
    cm[bh * SS + k] = m;
    cs[bh * SS + k] = s;
}

// ---------------- attention output: o[q,d] = sum_k softmax_col(w)[q,k]*kv[k,d] ---
// grid (S/128, BH), 256 threads, M-tile 128, N=96, BK=16, 8x6 microtile
__global__ __launch_bounds__(256)
void attnout_kernel(const float* __restrict__ w, const float* __restrict__ kv,
                    const float* __restrict__ cm, const float* __restrict__ cs,
                    float* __restrict__ o)
{
    __shared__ float Ps[16][132];
    __shared__ float Vs[16][96];
    __shared__ float sm[SS];
    __shared__ float si[SS];

    const int bh = blockIdx.y;
    const int b  = bh >> 3, h = bh & 7;
    const int q0 = blockIdx.x << 7;
    const int tid = threadIdx.x;
    const int tx = tid & 15, ty = tid >> 4;

    for (int i = tid; i < SS; i += 256) {
        sm[i] = cm[bh * SS + i];
        si[i] = 1.0f / cs[bh * SS + i];
    }
    __syncthreads();

    float acc[8][6];
#pragma unroll
    for (int i = 0; i < 8; i++)
#pragma unroll
        for (int j = 0; j < 6; j++) acc[i][j] = 0.f;

    const float* wb = w  + (size_t)bh * SS * SS + (size_t)q0 * SS;
    const float* vb = kv + (size_t)b * SS * DD + h * DKK;

    for (int k0 = 0; k0 < SS; k0 += 16) {
#pragma unroll
        for (int it = 0; it < 8; it++) {
            int idx = tid + (it << 8);
            int r = idx >> 4, kc = idx & 15;
            int kg = k0 + kc;
            float v = wb[(size_t)r * SS + kg];
            Ps[kc][r] = __expf(v - sm[kg]) * si[kg];
        }
#pragma unroll
        for (int it = 0; it < 6; it++) {
            int idx = tid + (it << 8);
            int r = idx / 96, d = idx % 96;
            Vs[r][d] = vb[(size_t)(k0 + r) * DD + d];
        }
        __syncthreads();
#pragma unroll
        for (int kk = 0; kk < 16; kk++) {
            float a[8], bb[6];
            *(float4*)(&a[0]) = *(const float4*)(&Ps[kk][ty << 3]);
            *(float4*)(&a[4]) = *(const float4*)(&Ps[kk][(ty << 3) + 4]);
#pragma unroll
            for (int j = 0; j < 6; j++) bb[j] = Vs[kk][tx * 6 + j];
#pragma unroll
            for (int i = 0; i < 8; i++)
#pragma unroll
                for (int j = 0; j < 6; j++)
                    acc[i][j] += a[i] * bb[j];
        }
        __syncthreads();
    }

#pragma unroll
    for (int i = 0; i < 8; i++) {
        int row = b * SS + q0 + (ty << 3) + i;
        float* op = o + (size_t)row * DD + h * DKK + tx * 6;
#pragma unroll
        for (int j = 0; j < 6; j++) op[j] = acc[i][j];
    }
}

// ---------------- residual add + layernorm over D=768 ---------------------------
__global__ __launch_bounds__(256)
void addln_kernel(const float* __restrict__ a, const float* __restrict__ r,
                  const float* __restrict__ g, const float* __restrict__ beta,
                  float* __restrict__ out)
{
    const int row = blockIdx.x;
    const int tid = threadIdx.x;
    const float* ap = a + (size_t)row * DD;
    const float* rp = r + (size_t)row * DD;

    float v[3];
    float sum = 0.f, sq = 0.f;
#pragma unroll
    for (int i = 0; i < 3; i++) {
        int c = tid + (i << 8);
        v[i] = ap[c] + rp[c];
        sum += v[i];
        sq  += v[i] * v[i];
    }
#pragma unroll
    for (int off = 16; off > 0; off >>= 1) {
        sum += __shfl_xor_sync(0xffffffffu, sum, off);
        sq  += __shfl_xor_sync(0xffffffffu, sq,  off);
    }
    __shared__ float s1[8], s2[8];
    int warp = tid >> 5, lane = tid & 31;
    if (lane == 0) { s1[warp] = sum; s2[warp] = sq; }
    __syncthreads();
    if (warp == 0) {
        float aa = (lane < 8) ? s1[lane] : 0.f;
        float bb = (lane < 8) ? s2[lane] : 0.f;
#pragma unroll
        for (int off = 4; off > 0; off >>= 1) {
            aa += __shfl_xor_sync(0xffffffffu, aa, off);
            bb += __shfl_xor_sync(0xffffffffu, bb, off);
        }
        if (lane == 0) { s1[0] = aa; s2[0] = bb; }
    }
    __syncthreads();
    const float invD = 1.0f / 768.0f;
    float mean = s1[0] * invD;
    float var  = s2[0] * invD - mean * mean;
    float inv  = rsqrtf(var + 1e-5f);
#pragma unroll
    for (int i = 0; i < 3; i++) {
        int c = tid + (i << 8);
        out[(size_t)row * DD + c] = (v[i] - mean) * inv * g[c] + beta[c];
    }
}

// ---------------- host side ------------------------------------------------------
static void run_mha(const float* xin,
                    const float* Wq, const float* bq,
                    const float* Wv, const float* bv,
                    const float* g, const float* beta,
                    float* q, float* kv, float* w, float* cm, float* cs,
                    float* o, float* xout)
{
    sgemm_bias<false><<<dim3(DD / 128, NR / 128), 256>>>(xin, Wq, bq, q, NR, DD, DD);
    sgemm_bias<false><<<dim3(DD / 128, NR / 128), 256>>>(xin, Wv, bv, kv, NR, DD, DD);
    scores_kernel<<<dim3(SS / 64, SS / 64, NBH), 256>>>(q, kv, w);
    colstats_kernel<<<dim3(SS / 256, NBH), 256>>>(w, cm, cs);
    attnout_kernel<<<dim3(SS / 128, NBH), 256>>>(w, kv, cm, cs, o);
    addln_kernel<<<NR, 256>>>(o, xin, g, beta, xout);
}

extern "C" void kernel_launch(void* const* d_in, const int* in_sizes, int n_in,
                              void* d_out, int out_size)
{
    (void)in_sizes; (void)n_in; (void)out_size;

    const float* x     = (const float*)d_in[0];
    const void*  amraw = d_in[1];
    const float* a1_Wq = (const float*)d_in[2];
    const float* a1_bq = (const float*)d_in[3];
    const float* a1_Wv = (const float*)d_in[4];
    const float* a1_bv = (const float*)d_in[5];
    const float* a1_g  = (const float*)d_in[6];
    const float* a1_b  = (const float*)d_in[7];
    const float* a2_Wq = (const float*)d_in[8];
    const float* a2_bq = (const float*)d_in[9];
    const float* a2_Wv = (const float*)d_in[10];
    const float* a2_bv = (const float*)d_in[11];
    const float* a2_g  = (const float*)d_in[12];
    const float* a2_b  = (const float*)d_in[13];
    const float* f_W1  = (const float*)d_in[14];
    const float* f_b1  = (const float*)d_in[15];
    const float* f_W2  = (const float*)d_in[16];
    const float* f_b2  = (const float*)d_in[17];
    const float* f_g   = (const float*)d_in[18];
    const float* f_b   = (const float*)d_in[19];
    float* out = (float*)d_out;

    float *q, *kv, *w, *cm, *cs, *o, *x1, *x2, *hbuf;
    cudaGetSymbolAddress((void**)&q,    g_q);
    cudaGetSymbolAddress((void**)&kv,   g_kv);
    cudaGetSymbolAddress((void**)&w,    g_w);
    cudaGetSymbolAddress((void**)&cm,   g_cm);
    cudaGetSymbolAddress((void**)&cs,   g_cs);
    cudaGetSymbolAddress((void**)&o,    g_o);
    cudaGetSymbolAddress((void**)&x1,   g_x1);
    cudaGetSymbolAddress((void**)&x2,   g_x2);
    cudaGetSymbolAddress((void**)&hbuf, g_h);

    // canonicalize the attention mask (robust to uint8 / int32 / float32 delivery)
    detect_mask_kernel<<<1, 256>>>((const unsigned char*)amraw);
    convert_mask_kernel<<<NR / 256, 256>>>(amraw);

    // layer 1 + layer 2 MHA
    run_mha(x,  a1_Wq, a1_bq, a1_Wv, a1_bv, a1_g, a1_b, q, kv, w, cm, cs, o, x1);
    run_mha(x1, a2_Wq, a2_bq, a2_Wv, a2_bv, a2_g, a2_b, q, kv, w, cm, cs, o, x2);

    // FFN
    sgemm_bias<true ><<<dim3(FFD / 128, NR / 128), 256>>>(x2, f_W1, f_b1, hbuf, NR, FFD, DD);
    sgemm_bias<false><<<dim3(DD  / 128, NR / 128), 256>>>(hbuf, f_W2, f_b2, o, NR, DD, FFD);
    addln_kernel<<<NR, 256>>>(o, x2, f_g, f_b, out);
}

// round 9
// speedup vs baseline: 1.3818x; 1.3818x over previous
#include <cuda_runtime.h>
#include <cuda_bf16.h>
#include <cstdint>

#define BB   8
#define SS   1024
#define DD   768
#define HH   8
#define DKK  96
#define FFD  1024
#define NR   (BB * SS)        // 8192 rows
#define NBH  (BB * HH)        // 64 (b,h) pairs

// ---------------- scratch (static device globals; no allocation) ----------------
__device__ float g_q [NR * DD];
__device__ float g_kv[NR * DD];
__device__ float g_w [(size_t)NBH * SS * SS];   // 268 MB score matrix
__device__ float g_cm[NBH * SS];
__device__ float g_cs[NBH * SS];
__device__ float g_o [NR * DD];
__device__ float g_x1[NR * DD];
__device__ float g_x2[NR * DD];
__device__ float g_h [NR * FFD];
__device__ unsigned char g_mask[NR];
__device__ int g_flags[2];
__device__ __nv_bfloat16 g_a2 [(size_t)NR * 3 * 1024];    // split A  (max K'=3072)
__device__ __nv_bfloat16 g_b2t[(size_t)1024 * 3 * 1024];  // split W^T (max N=1024,K'=3072)

#define SWZ128(o) ((o) ^ (((o) >> 3) & 0x70))

__device__ __forceinline__ uint32_t smem_u32(const void* p) {
    uint32_t a;
    asm("{ .reg .u64 t; cvta.to.shared.u64 t, %1; cvt.u32.u64 %0, t; }" : "=r"(a) : "l"(p));
    return a;
}

// ================= bf16 split conversions =======================================
// A2[r, 0..K)=hi  A2[r, K..2K)=hi  A2[r, 2K..3K)=lo
__global__ void split_a_kernel(const float* __restrict__ X,
                               __nv_bfloat16* __restrict__ A2, int K)
{
    int idx = blockIdx.x * 256 + threadIdx.x;   // over M*K
    int r = idx / K, k = idx - r * K;
    float v = X[idx];
    __nv_bfloat16 h = __float2bfloat16(v);
    __nv_bfloat16 l = __float2bfloat16(v - __bfloat162float(h));
    __nv_bfloat16* row = A2 + (size_t)r * 3 * K;
    row[k] = h; row[K + k] = h; row[2 * K + k] = l;
}

// Bt[n, 0..K)=hi(W[:,n])  Bt[n, K..2K)=lo  Bt[n, 2K..3K)=hi   (pairs with A's hi,hi,lo)
__global__ void split_wt_kernel(const float* __restrict__ W,
                                __nv_bfloat16* __restrict__ Bt, int K, int N)
{
    __shared__ float t[32][33];
    int nb = blockIdx.x * 32, kb = blockIdx.y * 32;
    int x = threadIdx.x, y = threadIdx.y;          // 32 x 8
#pragma unroll
    for (int yy = 0; yy < 32; yy += 8)
        t[y + yy][x] = W[(size_t)(kb + y + yy) * N + nb + x];
    __syncthreads();
    const size_t K3 = 3 * (size_t)K;
#pragma unroll
    for (int yy = 0; yy < 32; yy += 8) {
        int n = nb + y + yy;
        int k = kb + x;
        float v = t[x][y + yy];
        __nv_bfloat16 h = __float2bfloat16(v);
        __nv_bfloat16 l = __float2bfloat16(v - __bfloat162float(h));
        Bt[(size_t)n * K3 + k] = h;
        Bt[(size_t)n * K3 + K + k] = l;
        Bt[(size_t)n * K3 + 2 * K + k] = h;
    }
}

// ================= HMMA GEMM: C[M,N] = A2[M,Kp] @ Bt[N,Kp]^T + bias =============
// CTA 128x128, BK=64 bf16, 8 warps (2x4), warp tile 64x32 via m16n8k16.
// SMEM: 2 stages x (A 16KB + B 16KB) = 64KB dynamic, SW128 swizzle (ldmatrix-safe)
#define GEMM_SMEM_BYTES 65536

template <bool RELU>
__global__ __launch_bounds__(256)
void mma_gemm(const __nv_bfloat16* __restrict__ A2, const __nv_bfloat16* __restrict__ Bt,
              const float* __restrict__ bias, float* __restrict__ C, int N, int Kp)
{
    extern __shared__ char smem[];
    const uint32_t sb = smem_u32(smem);
    const int tid = threadIdx.x, wid = tid >> 5, lid = tid & 31;
    const int row0 = blockIdx.y << 7, col0 = blockIdx.x << 7;
    const int wr = (wid & 1) << 6;        // warp row base   (0 / 64)
    const int wc = (wid >> 1) << 5;       // warp col base   (0/32/64/96)

    // global load mapping: per tile, thread covers 4 uint4 (rows of 64 bf16 = 8 x16B)
    const int gr = tid >> 3;              // 0..31 (+t*32)
    const int gc = tid & 7;               // 16B chunk within row

    // ldmatrix lane address components
    const int a_row = (lid & 7) + ((lid >> 3) & 1) * 8;   // row within 16
    const int a_kb  = (lid >> 4) * 8;                     // k sub-block (0/8)
    const int b_row = (lid & 7);                          // n within 8 (lanes 0-15 used)
    const int b_kb  = ((lid >> 3) & 1) * 8;

    float acc[4][4][4];
#pragma unroll
    for (int mi = 0; mi < 4; mi++)
#pragma unroll
        for (int ni = 0; ni < 4; ni++)
#pragma unroll
            for (int r = 0; r < 4; r++) acc[mi][ni][r] = 0.f;

    const int niter = Kp >> 6;

    // ---- preload stage 0
    {
        const __nv_bfloat16* Ag = A2 + (size_t)row0 * Kp;
        const __nv_bfloat16* Bg = Bt + (size_t)col0 * Kp;
#pragma unroll
        for (int t = 0; t < 4; t++) {
            int r = gr + (t << 5);
            uint32_t off = (uint32_t)((r << 7) + (gc << 4));
            *(uint4*)(smem + SWZ128(off)) =
                *(const uint4*)(Ag + (size_t)r * Kp + (gc << 3));
            *(uint4*)(smem + 16384 + SWZ128(off)) =
                *(const uint4*)(Bg + (size_t)r * Kp + (gc << 3));
        }
    }
    __syncthreads();

    for (int i = 0; i < niter; i++) {
        // ---- stage i+1 global loads into registers
        uint4 ra[4], rb[4];
        if (i + 1 < niter) {
            const __nv_bfloat16* Ag = A2 + (size_t)row0 * Kp + ((i + 1) << 6);
            const __nv_bfloat16* Bg = Bt + (size_t)col0 * Kp + ((i + 1) << 6);
#pragma unroll
            for (int t = 0; t < 4; t++) {
                int r = gr + (t << 5);
                ra[t] = *(const uint4*)(Ag + (size_t)r * Kp + (gc << 3));
                rb[t] = *(const uint4*)(Bg + (size_t)r * Kp + (gc << 3));
            }
        }

        // ---- compute on stage i
        const uint32_t sA = sb + (uint32_t)((i & 1) * 32768);
        const uint32_t sB = sA + 16384;
#pragma unroll
        for (int kk = 0; kk < 4; kk++) {
            uint32_t af[4][4], bf[4][2];
#pragma unroll
            for (int mi = 0; mi < 4; mi++) {
                uint32_t off = (uint32_t)(((wr + mi * 16 + a_row) << 7) +
                                          ((kk * 16 + a_kb) << 1));
                uint32_t addr = sA + SWZ128(off);
                asm volatile("ldmatrix.sync.aligned.m8n8.x4.shared.b16 {%0,%1,%2,%3}, [%4];"
                             : "=r"(af[mi][0]), "=r"(af[mi][1]), "=r"(af[mi][2]), "=r"(af[mi][3])
                             : "r"(addr));
            }
#pragma unroll
            for (int ni = 0; ni < 4; ni++) {
                uint32_t off = (uint32_t)(((wc + ni * 8 + b_row) << 7) +
                                          ((kk * 16 + b_kb) << 1));
                uint32_t addr = sB + SWZ128(off);
                asm volatile("ldmatrix.sync.aligned.m8n8.x2.shared.b16 {%0,%1}, [%2];"
                             : "=r"(bf[ni][0]), "=r"(bf[ni][1])
                             : "r"(addr));
            }
#pragma unroll
            for (int mi = 0; mi < 4; mi++)
#pragma unroll
                for (int ni = 0; ni < 4; ni++) {
                    asm volatile(
                        "mma.sync.aligned.m16n8k16.row.col.f32.bf16.bf16.f32 "
                        "{%0,%1,%2,%3}, {%4,%5,%6,%7}, {%8,%9}, {%0,%1,%2,%3};"
                        : "+f"(acc[mi][ni][0]), "+f"(acc[mi][ni][1]),
                          "+f"(acc[mi][ni][2]), "+f"(acc[mi][ni][3])
                        : "r"(af[mi][0]), "r"(af[mi][1]), "r"(af[mi][2]), "r"(af[mi][3]),
                          "r"(bf[ni][0]), "r"(bf[ni][1]));
                }
        }

        // ---- store stage i+1
        if (i + 1 < niter) {
            char* dst = smem + ((i + 1) & 1) * 32768;
#pragma unroll
            for (int t = 0; t < 4; t++) {
                int r = gr + (t << 5);
                uint32_t off = (uint32_t)((r << 7) + (gc << 4));
                *(uint4*)(dst + SWZ128(off)) = ra[t];
                *(uint4*)(dst + 16384 + SWZ128(off)) = rb[t];
            }
        }
        __syncthreads();
    }

    // ---- epilogue
    const int l4 = lid >> 2, l2 = (lid & 3) << 1;
#pragma unroll
    for (int mi = 0; mi < 4; mi++) {
#pragma unroll
        for (int ni = 0; ni < 4; ni++) {
            int rg = row0 + wr + mi * 16 + l4;
            int cg = col0 + wc + ni * 8 + l2;
            float b0 = bias[cg], b1 = bias[cg + 1];
            float2 v0 = make_float2(acc[mi][ni][0] + b0, acc[mi][ni][1] + b1);
            float2 v1 = make_float2(acc[mi][ni][2] + b0, acc[mi][ni][3] + b1);
            if (RELU) {
                v0.x = fmaxf(v0.x, 0.f); v0.y = fmaxf(v0.y, 0.f);
                v1.x = fmaxf(v1.x, 0.f); v1.y = fmaxf(v1.y, 0.f);
            }
            *(float2*)(C + (size_t)rg * N + cg) = v0;
            *(float2*)(C + (size_t)(rg + 8) * N + cg) = v1;
        }
    }
}

// ================= mask canonicalization ========================================
__global__ void detect_mask_kernel(const unsigned char* __restrict__ m)
{
    __shared__ int s_big, s_mis;
    if (threadIdx.x == 0) { s_big = 0; s_mis = 0; }
    __syncthreads();
    int big = 0, mis = 0;
    for (int i = threadIdx.x; i < NR; i += blockDim.x) {
        unsigned char v = m[i];
        if (v > 1) big = 1;
        if ((i & 3) != 0 && v != 0) mis = 1;
    }
    if (big) atomicOr(&s_big, 1);
    if (mis) atomicOr(&s_mis, 1);
    __syncthreads();
    if (threadIdx.x == 0) { g_flags[0] = s_big; g_flags[1] = s_mis; }
}

__global__ void convert_mask_kernel(const void* __restrict__ m)
{
    int i = blockIdx.x * blockDim.x + threadIdx.x;
    bool word32 = (g_flags[0] != 0) || (g_flags[1] == 0);
    unsigned char out;
    if (word32) out = (((const unsigned int*)m)[i] != 0u) ? 1 : 0;
    else        out = (((const unsigned char*)m)[i] != 0) ? 1 : 0;
    g_mask[i] = out;
}

// ================= attention (SIMT, unchanged from passing round) ===============
__global__ __launch_bounds__(256)
void scores_kernel(const float* __restrict__ q, const float* __restrict__ kv,
                   float* __restrict__ w)
{
    const int bh = blockIdx.z;
    const int b  = bh >> 3, h = bh & 7;
    const int k0 = blockIdx.x << 6;
    const int q0 = blockIdx.y << 6;
    const int tid = threadIdx.x;
    const int tx = tid & 15, ty = tid >> 4;

    float* wrow = w + (size_t)bh * SS * SS;

    if (k0 > q0 + 63) {
        const float4 neg = make_float4(-1e9f, -1e9f, -1e9f, -1e9f);
#pragma unroll
        for (int i = 0; i < 4; i++) {
            int qi = q0 + (ty << 2) + i;
            *(float4*)(wrow + (size_t)qi * SS + k0 + (tx << 2)) = neg;
        }
        return;
    }

    __shared__ float Qs[32][68];
    __shared__ float Ks[32][68];

    float acc[4][4];
#pragma unroll
    for (int i = 0; i < 4; i++)
#pragma unroll
        for (int j = 0; j < 4; j++) acc[i][j] = 0.f;

    const float* qb = q  + (size_t)(b * SS + q0) * DD + h * DKK;
    const float* kb = kv + (size_t)(b * SS + k0) * DD + h * DKK;

    for (int c = 0; c < 3; c++) {
#pragma unroll
        for (int it = 0; it < 8; it++) {
            int idx = tid + (it << 8);
            int r = idx >> 5, d = idx & 31;
            Qs[d][r] = qb[(size_t)r * DD + c * 32 + d];
            Ks[d][r] = kb[(size_t)r * DD + c * 32 + d];
        }
        __syncthreads();
#pragma unroll
        for (int kk = 0; kk < 32; kk++) {
            float a[4], bb[4];
            *(float4*)(&a[0])  = *(const float4*)(&Qs[kk][ty << 2]);
            *(float4*)(&bb[0]) = *(const float4*)(&Ks[kk][tx << 2]);
#pragma unroll
            for (int i = 0; i < 4; i++)
#pragma unroll
                for (int j = 0; j < 4; j++)
                    acc[i][j] += a[i] * bb[j];
        }
        __syncthreads();
    }

    const float scale = 0.10206207261596577f;
#pragma unroll
    for (int i = 0; i < 4; i++) {
        int qi = q0 + (ty << 2) + i;
        bool pm = (g_mask[b * SS + qi] != 0);
        float vv[4];
#pragma unroll
        for (int j = 0; j < 4; j++) {
            int ki = k0 + (tx << 2) + j;
            float v = acc[i][j] * scale;
            if (pm || ki > qi) v = -1e9f;
            vv[j] = v;
        }
        float4 o = make_float4(vv[0], vv[1], vv[2], vv[3]);
        *(float4*)(wrow + (size_t)qi * SS + k0 + (tx << 2)) = o;
    }
}

__global__ __launch_bounds__(256)
void colstats_kernel(const float* __restrict__ w, float* __restrict__ cm,
                     float* __restrict__ cs)
{
    const int bh = blockIdx.y;
    const int k  = (blockIdx.x << 8) + threadIdx.x;
    const float* wb = w + (size_t)bh * SS * SS + k;
    float m = __int_as_float(0xff800000);
    float s = 0.f;
    for (int qq = 0; qq < SS; qq++) {
        float v = wb[(size_t)qq * SS];
        if (v > m) { s = s * __expf(m - v) + 1.0f; m = v; }
        else       { s += __expf(v - m); }
    }
    cm[bh * SS + k] = m;
    cs[bh * SS + k] = s;
}

__global__ __launch_bounds__(256)
void attnout_kernel(const float* __restrict__ w, const float* __restrict__ kv,
                    const float* __restrict__ cm, const float* __restrict__ cs,
                    float* __restrict__ o)
{
    __shared__ float Ps[16][132];
    __shared__ float Vs[16][96];
    __shared__ float sm[SS];
    __shared__ float si[SS];

    const int bh = blockIdx.y;
    const int b  = bh >> 3, h = bh & 7;
    const int q0 = blockIdx.x << 7;
    const int tid = threadIdx.x;
    const int tx = tid & 15, ty = tid >> 4;

    for (int i = tid; i < SS; i += 256) {
        sm[i] = cm[bh * SS + i];
        si[i] = 1.0f / cs[bh * SS + i];
    }
    __syncthreads();

    float acc[8][6];
#pragma unroll
    for (int i = 0; i < 8; i++)
#pragma unroll
        for (int j = 0; j < 6; j++) acc[i][j] = 0.f;

    const float* wb = w  + (size_t)bh * SS * SS + (size_t)q0 * SS;
    const float* vb = kv + (size_t)b * SS * DD + h * DKK;

    for (int k0 = 0; k0 < SS; k0 += 16) {
#pragma unroll
        for (int it = 0; it < 8; it++) {
            int idx = tid + (it << 8);
            int r = idx >> 4, kc = idx & 15;
            int kg = k0 + kc;
            float v = wb[(size_t)r * SS + kg];
            Ps[kc][r] = __expf(v - sm[kg]) * si[kg];
        }
#pragma unroll
        for (int it = 0; it < 6; it++) {
            int idx = tid + (it << 8);
            int r = idx / 96, d = idx % 96;
            Vs[r][d] = vb[(size_t)(k0 + r) * DD + d];
        }
        __syncthreads();
#pragma unroll
        for (int kk = 0; kk < 16; kk++) {
            float a[8], bb[6];
            *(float4*)(&a[0]) = *(const float4*)(&Ps[kk][ty << 3]);
            *(float4*)(&a[4]) = *(const float4*)(&Ps[kk][(ty << 3) + 4]);
#pragma unroll
            for (int j = 0; j < 6; j++) bb[j] = Vs[kk][tx * 6 + j];
#pragma unroll
            for (int i = 0; i < 8; i++)
#pragma unroll
                for (int j = 0; j < 6; j++)
                    acc[i][j] += a[i] * bb[j];
        }
        __syncthreads();
    }

#pragma unroll
    for (int i = 0; i < 8; i++) {
        int row = b * SS + q0 + (ty << 3) + i;
        float* op = o + (size_t)row * DD + h * DKK + tx * 6;
#pragma unroll
        for (int j = 0; j < 6; j++) op[j] = acc[i][j];
    }
}

__global__ __launch_bounds__(256)
void addln_kernel(const float* __restrict__ a, const float* __restrict__ r,
                  const float* __restrict__ g, const float* __restrict__ beta,
                  float* __restrict__ out)
{
    const int row = blockIdx.x;
    const int tid = threadIdx.x;
    const float* ap = a + (size_t)row * DD;
    const float* rp = r + (size_t)row * DD;

    float v[3];
    float sum = 0.f, sq = 0.f;
#pragma unroll
    for (int i = 0; i < 3; i++) {
        int c = tid + (i << 8);
        v[i] = ap[c] + rp[c];
        sum += v[i];
        sq  += v[i] * v[i];
    }
#pragma unroll
    for (int off = 16; off > 0; off >>= 1) {
        sum += __shfl_xor_sync(0xffffffffu, sum, off);
        sq  += __shfl_xor_sync(0xffffffffu, sq,  off);
    }
    __shared__ float s1[8], s2[8];
    int warp = tid >> 5, lane = tid & 31;
    if (lane == 0) { s1[warp] = sum; s2[warp] = sq; }
    __syncthreads();
    if (warp == 0) {
        float aa = (lane < 8) ? s1[lane] : 0.f;
        float bb = (lane < 8) ? s2[lane] : 0.f;
#pragma unroll
        for (int off = 4; off > 0; off >>= 1) {
            aa += __shfl_xor_sync(0xffffffffu, aa, off);
            bb += __shfl_xor_sync(0xffffffffu, bb, off);
        }
        if (lane == 0) { s1[0] = aa; s2[0] = bb; }
    }
    __syncthreads();
    const float invD = 1.0f / 768.0f;
    float mean = s1[0] * invD;
    float var  = s2[0] * invD - mean * mean;
    float inv  = rsqrtf(var + 1e-5f);
#pragma unroll
    for (int i = 0; i < 3; i++) {
        int c = tid + (i << 8);
        out[(size_t)row * DD + c] = (v[i] - mean) * inv * g[c] + beta[c];
    }
}

// ================= host side ====================================================
static void run_mha(const float* xin,
                    const float* Wq, const float* bq,
                    const float* Wv, const float* bv,
                    const float* g, const float* beta,
                    __nv_bfloat16* a2, __nv_bfloat16* b2t,
                    float* q, float* kv, float* w, float* cm, float* cs,
                    float* o, float* xout)
{
    split_a_kernel<<<NR * DD / 256, 256>>>(xin, a2, DD);
    split_wt_kernel<<<dim3(DD / 32, DD / 32), dim3(32, 8)>>>(Wq, b2t, DD, DD);
    mma_gemm<false><<<dim3(DD / 128, NR / 128), 256, GEMM_SMEM_BYTES>>>(a2, b2t, bq, q, DD, 3 * DD);
    split_wt_kernel<<<dim3(DD / 32, DD / 32), dim3(32, 8)>>>(Wv, b2t, DD, DD);
    mma_gemm<false><<<dim3(DD / 128, NR / 128), 256, GEMM_SMEM_BYTES>>>(a2, b2t, bv, kv, DD, 3 * DD);
    scores_kernel<<<dim3(SS / 64, SS / 64, NBH), 256>>>(q, kv, w);
    colstats_kernel<<<dim3(SS / 256, NBH), 256>>>(w, cm, cs);
    attnout_kernel<<<dim3(SS / 128, NBH), 256>>>(w, kv, cm, cs, o);
    addln_kernel<<<NR, 256>>>(o, xin, g, beta, xout);
}

extern "C" void kernel_launch(void* const* d_in, const int* in_sizes, int n_in,
                              void* d_out, int out_size)
{
    (void)in_sizes; (void)n_in; (void)out_size;

    const float* x     = (const float*)d_in[0];
    const void*  amraw = d_in[1];
    const float* a1_Wq = (const float*)d_in[2];
    const float* a1_bq = (const float*)d_in[3];
    const float* a1_Wv = (const float*)d_in[4];
    const float* a1_bv = (const float*)d_in[5];
    const float* a1_g  = (const float*)d_in[6];
    const float* a1_b  = (const float*)d_in[7];
    const float* a2_Wq = (const float*)d_in[8];
    const float* a2_bq = (const float*)d_in[9];
    const float* a2_Wv = (const float*)d_in[10];
    const float* a2_bv = (const float*)d_in[11];
    const float* a2_g  = (const float*)d_in[12];
    const float* a2_b  = (const float*)d_in[13];
    const float* f_W1  = (const float*)d_in[14];
    const float* f_b1  = (const float*)d_in[15];
    const float* f_W2  = (const float*)d_in[16];
    const float* f_b2  = (const float*)d_in[17];
    const float* f_g   = (const float*)d_in[18];
    const float* f_b   = (const float*)d_in[19];
    float* out = (float*)d_out;

    float *q, *kv, *w, *cm, *cs, *o, *x1, *x2, *hbuf;
    __nv_bfloat16 *a2buf, *b2t;
    cudaGetSymbolAddress((void**)&q,     g_q);
    cudaGetSymbolAddress((void**)&kv,    g_kv);
    cudaGetSymbolAddress((void**)&w,     g_w);
    cudaGetSymbolAddress((void**)&cm,    g_cm);
    cudaGetSymbolAddress((void**)&cs,    g_cs);
    cudaGetSymbolAddress((void**)&o,     g_o);
    cudaGetSymbolAddress((void**)&x1,    g_x1);
    cudaGetSymbolAddress((void**)&x2,    g_x2);
    cudaGetSymbolAddress((void**)&hbuf,  g_h);
    cudaGetSymbolAddress((void**)&a2buf, g_a2);
    cudaGetSymbolAddress((void**)&b2t,   g_b2t);

    cudaFuncSetAttribute(mma_gemm<false>, cudaFuncAttributeMaxDynamicSharedMemorySize, GEMM_SMEM_BYTES);
    cudaFuncSetAttribute(mma_gemm<true >, cudaFuncAttributeMaxDynamicSharedMemorySize, GEMM_SMEM_BYTES);

    // canonicalize the attention mask (robust to uint8 / int32 / float32 delivery)
    detect_mask_kernel<<<1, 256>>>((const unsigned char*)amraw);
    convert_mask_kernel<<<NR / 256, 256>>>(amraw);

    // layer 1 + layer 2 MHA
    run_mha(x,  a1_Wq, a1_bq, a1_Wv, a1_bv, a1_g, a1_b, a2buf, b2t, q, kv, w, cm, cs, o, x1);
    run_mha(x1, a2_Wq, a2_bq, a2_Wv, a2_bv, a2_g, a2_b, a2buf, b2t, q, kv, w, cm, cs, o, x2);

    // FFN
    split_a_kernel<<<NR * DD / 256, 256>>>(x2, a2buf, DD);
    split_wt_kernel<<<dim3(FFD / 32, DD / 32), dim3(32, 8)>>>(f_W1, b2t, DD, FFD);
    mma_gemm<true ><<<dim3(FFD / 128, NR / 128), 256, GEMM_SMEM_BYTES>>>(a2buf, b2t, f_b1, hbuf, FFD, 3 * DD);
    split_a_kernel<<<NR * FFD / 256, 256>>>(hbuf, a2buf, FFD);
    split_wt_kernel<<<dim3(DD / 32, FFD / 32), dim3(32, 8)>>>(f_W2, b2t, FFD, DD);
    mma_gemm<false><<<dim3(DD / 128, NR / 128), 256, GEMM_SMEM_BYTES>>>(a2buf, b2t, f_b2, o, DD, 3 * FFD);
    addln_kernel<<<NR, 256>>>(o, x2, f_g, f_b, out);
}

// round 13
// speedup vs baseline: 1.6241x; 1.1753x over previous
#include <cuda_runtime.h>
#include <cuda_bf16.h>
#include <cstdint>

#define BB   8
#define SS   1024
#define DD   768
#define HH   8
#define DKK  96
#define FFD  1024
#define NR   (BB * SS)        // 8192 rows
#define NBH  (BB * HH)        // 64 (b,h) pairs

// ---------------- scratch (static device globals; no allocation) ----------------
__device__ float g_q [NR * DD];
__device__ float g_kv[NR * DD];
__device__ float g_w [(size_t)NBH * SS * SS];   // 268 MB score matrix (fp32)
__device__ float g_cm[NBH * SS];
__device__ float g_cs[NBH * SS];
__device__ float g_o [NR * DD];
__device__ float g_x1[NR * DD];
__device__ float g_x2[NR * DD];
__device__ float g_h [NR * FFD];
__device__ unsigned char g_mask[NR];
__device__ int g_flags[2];
__device__ __nv_bfloat16 g_a2 [(size_t)NR * 3 * 1024];    // split A  (dense GEMMs)
__device__ __nv_bfloat16 g_b2t[(size_t)1024 * 3 * 1024];  // split W^T (dense GEMMs)
__device__ __nv_bfloat16 g_qs [(size_t)NBH * SS * 384];   // q  split [hi|hi|lo], DK pad 128
__device__ __nv_bfloat16 g_ks [(size_t)NBH * SS * 384];   // kv split [hi|lo|hi], DK pad 128
__device__ __nv_bfloat16 g_p  [(size_t)NBH * SS * 2048];  // P  split [hi|lo] (268 MB)
__device__ __nv_bfloat16 g_vt [(size_t)BB * DD * 3072];   // V^T split [hi|lo|hi] per batch

#define SWZ128(o) ((o) ^ (((o) >> 3) & 0x70))

__device__ __forceinline__ uint32_t smem_u32(const void* p) {
    uint32_t a;
    asm("{ .reg .u64 t; cvta.to.shared.u64 t, %1; cvt.u32.u64 %0, t; }" : "=r"(a) : "l"(p));
    return a;
}

// ================= bf16 split conversions (dense GEMM path) =====================
__global__ void split_a_kernel(const float* __restrict__ X,
                               __nv_bfloat16* __restrict__ A2, int K)
{
    int idx = blockIdx.x * 256 + threadIdx.x;
    int r = idx / K, k = idx - r * K;
    float v = X[idx];
    __nv_bfloat16 h = __float2bfloat16(v);
    __nv_bfloat16 l = __float2bfloat16(v - __bfloat162float(h));
    __nv_bfloat16* row = A2 + (size_t)r * 3 * K;
    row[k] = h; row[K + k] = h; row[2 * K + k] = l;
}

__global__ void split_wt_kernel(const float* __restrict__ W,
                                __nv_bfloat16* __restrict__ Bt, int K, int N)
{
    __shared__ float t[32][33];
    int nb = blockIdx.x * 32, kb = blockIdx.y * 32;
    int x = threadIdx.x, y = threadIdx.y;          // 32 x 8
#pragma unroll
    for (int yy = 0; yy < 32; yy += 8)
        t[y + yy][x] = W[(size_t)(kb + y + yy) * N + nb + x];
    __syncthreads();
    const size_t K3 = 3 * (size_t)K;
#pragma unroll
    for (int yy = 0; yy < 32; yy += 8) {
        int n = nb + y + yy;
        int k = kb + x;
        float v = t[x][y + yy];
        __nv_bfloat16 h = __float2bfloat16(v);
        __nv_bfloat16 l = __float2bfloat16(v - __bfloat162float(h));
        Bt[(size_t)n * K3 + k] = h;
        Bt[(size_t)n * K3 + K + k] = l;
        Bt[(size_t)n * K3 + 2 * K + k] = h;
    }
}

// ================= attention split conversions ==================================
// q/kv [8192,768] -> per-(b,h) rows [s][384]: 3 planes of 128 (DK 96 zero-padded)
// PAIR 0: [hi|hi|lo] (A side)   PAIR 1: [hi|lo|hi] (B side)
template <int PAIR>
__global__ void split_qk_kernel(const float* __restrict__ src,
                                __nv_bfloat16* __restrict__ dst)
{
    int idx = blockIdx.x * 256 + threadIdx.x;       // over 8192*1024
    int row = idx >> 10, cp = idx & 1023;
    int h = cp >> 7, dd = cp & 127;
    float v = (dd < DKK) ? src[(size_t)row * DD + h * DKK + dd] : 0.f;
    __nv_bfloat16 hi = __float2bfloat16(v);
    __nv_bfloat16 lo = __float2bfloat16(v - __bfloat162float(hi));
    int b = row >> 10, s = row & 1023;
    __nv_bfloat16* out = dst + ((size_t)(b * HH + h) * SS + s) * 384 + dd;
    if (PAIR == 0) { out[0] = hi; out[128] = hi; out[256] = lo; }
    else           { out[0] = hi; out[128] = lo; out[256] = hi; }
}

// kv per batch [1024 k, 768 n] -> vt[b][n][3072] planes [hi|lo|hi]
__global__ void split_vt_kernel(const float* __restrict__ kv,
                                __nv_bfloat16* __restrict__ vt)
{
    __shared__ float t[32][33];
    int b = blockIdx.z;
    const float* W = kv + (size_t)b * SS * DD;
    __nv_bfloat16* Bt = vt + (size_t)b * DD * 3072;
    int nb = blockIdx.x * 32, kb = blockIdx.y * 32;
    int x = threadIdx.x, y = threadIdx.y;
#pragma unroll
    for (int yy = 0; yy < 32; yy += 8)
        t[y + yy][x] = W[(size_t)(kb + y + yy) * DD + nb + x];
    __syncthreads();
#pragma unroll
    for (int yy = 0; yy < 32; yy += 8) {
        int n = nb + y + yy;
        int k = kb + x;
        float v = t[x][y + yy];
        __nv_bfloat16 h = __float2bfloat16(v);
        __nv_bfloat16 l = __float2bfloat16(v - __bfloat162float(h));
        Bt[(size_t)n * 3072 + k] = h;
        Bt[(size_t)n * 3072 + 1024 + k] = l;
        Bt[(size_t)n * 3072 + 2048 + k] = h;
    }
}

// w + colstats -> P split [hi|lo] planes of 1024
__global__ void psplit_kernel(const float* __restrict__ w,
                              const float* __restrict__ cm,
                              const float* __restrict__ cs,
                              __nv_bfloat16* __restrict__ P)
{
    const int r = blockIdx.x;                 // bh*1024 + q
    const int bh = r >> 10;
    const int k4 = threadIdx.x << 2;
    float4 wv = *(const float4*)(w + (size_t)r * SS + k4);
    float4 m  = *(const float4*)(cm + bh * SS + k4);
    float4 s  = *(const float4*)(cs + bh * SS + k4);
    float p0 = __expf(wv.x - m.x) * __fdividef(1.f, s.x);
    float p1 = __expf(wv.y - m.y) * __fdividef(1.f, s.y);
    float p2 = __expf(wv.z - m.z) * __fdividef(1.f, s.z);
    float p3 = __expf(wv.w - m.w) * __fdividef(1.f, s.w);
    __nv_bfloat16 h[4], l[4];
    h[0] = __float2bfloat16(p0); l[0] = __float2bfloat16(p0 - __bfloat162float(h[0]));
    h[1] = __float2bfloat16(p1); l[1] = __float2bfloat16(p1 - __bfloat162float(h[1]));
    h[2] = __float2bfloat16(p2); l[2] = __float2bfloat16(p2 - __bfloat162float(h[2]));
    h[3] = __float2bfloat16(p3); l[3] = __float2bfloat16(p3 - __bfloat162float(h[3]));
    __nv_bfloat16* out = P + (size_t)r * 2048 + k4;
    *(uint2*)(out)        = *(uint2*)h;
    *(uint2*)(out + 1024) = *(uint2*)l;
}

// ================= HMMA dense GEMM (validated R9) ===============================
#define GEMM_SMEM_BYTES 65536

template <bool RELU>
__global__ __launch_bounds__(256)
void mma_gemm(const __nv_bfloat16* __restrict__ A2, const __nv_bfloat16* __restrict__ Bt,
              const float* __restrict__ bias, float* __restrict__ C, int N, int Kp)
{
    extern __shared__ char smem[];
    const uint32_t sb = smem_u32(smem);
    const int tid = threadIdx.x, wid = tid >> 5, lid = tid & 31;
    const int row0 = blockIdx.y << 7, col0 = blockIdx.x << 7;
    const int wr = (wid & 1) << 6;
    const int wc = (wid >> 1) << 5;

    const int gr = tid >> 3;
    const int gc = tid & 7;

    const int a_row = (lid & 7) + ((lid >> 3) & 1) * 8;
    const int a_kb  = (lid >> 4) * 8;
    const int b_row = (lid & 7);
    const int b_kb  = ((lid >> 3) & 1) * 8;

    float acc[4][4][4];
#pragma unroll
    for (int mi = 0; mi < 4; mi++)
#pragma unroll
        for (int ni = 0; ni < 4; ni++)
#pragma unroll
            for (int r = 0; r < 4; r++) acc[mi][ni][r] = 0.f;

    const int niter = Kp >> 6;

    {
        const __nv_bfloat16* Ag = A2 + (size_t)row0 * Kp;
        const __nv_bfloat16* Bg = Bt + (size_t)col0 * Kp;
#pragma unroll
        for (int t = 0; t < 4; t++) {
            int r = gr + (t << 5);
            uint32_t off = (uint32_t)((r << 7) + (gc << 4));
            *(uint4*)(smem + SWZ128(off)) =
                *(const uint4*)(Ag + (size_t)r * Kp + (gc << 3));
            *(uint4*)(smem + 16384 + SWZ128(off)) =
                *(const uint4*)(Bg + (size_t)r * Kp + (gc << 3));
        }
    }
    __syncthreads();

    for (int i = 0; i < niter; i++) {
        uint4 ra[4], rb[4];
        if (i + 1 < niter) {
            const __nv_bfloat16* Ag = A2 + (size_t)row0 * Kp + ((i + 1) << 6);
            const __nv_bfloat16* Bg = Bt + (size_t)col0 * Kp + ((i + 1) << 6);
#pragma unroll
            for (int t = 0; t < 4; t++) {
                int r = gr + (t << 5);
                ra[t] = *(const uint4*)(Ag + (size_t)r * Kp + (gc << 3));
                rb[t] = *(const uint4*)(Bg + (size_t)r * Kp + (gc << 3));
            }
        }

        const uint32_t sA = sb + (uint32_t)((i & 1) * 32768);
        const uint32_t sB = sA + 16384;
#pragma unroll
        for (int kk = 0; kk < 4; kk++) {
            uint32_t af[4][4], bf[4][2];
#pragma unroll
            for (int mi = 0; mi < 4; mi++) {
                uint32_t off = (uint32_t)(((wr + mi * 16 + a_row) << 7) +
                                          ((kk * 16 + a_kb) << 1));
                uint32_t addr = sA + SWZ128(off);
                asm volatile("ldmatrix.sync.aligned.m8n8.x4.shared.b16 {%0,%1,%2,%3}, [%4];"
                             : "=r"(af[mi][0]), "=r"(af[mi][1]), "=r"(af[mi][2]), "=r"(af[mi][3])
                             : "r"(addr));
            }
#pragma unroll
            for (int ni = 0; ni < 4; ni++) {
                uint32_t off = (uint32_t)(((wc + ni * 8 + b_row) << 7) +
                                          ((kk * 16 + b_kb) << 1));
                uint32_t addr = sB + SWZ128(off);
                asm volatile("ldmatrix.sync.aligned.m8n8.x2.shared.b16 {%0,%1}, [%2];"
                             : "=r"(bf[ni][0]), "=r"(bf[ni][1])
                             : "r"(addr));
            }
#pragma unroll
            for (int mi = 0; mi < 4; mi++)
#pragma unroll
                for (int ni = 0; ni < 4; ni++) {
                    asm volatile(
                        "mma.sync.aligned.m16n8k16.row.col.f32.bf16.bf16.f32 "
                        "{%0,%1,%2,%3}, {%4,%5,%6,%7}, {%8,%9}, {%0,%1,%2,%3};"
                        : "+f"(acc[mi][ni][0]), "+f"(acc[mi][ni][1]),
                          "+f"(acc[mi][ni][2]), "+f"(acc[mi][ni][3])
                        : "r"(af[mi][0]), "r"(af[mi][1]), "r"(af[mi][2]), "r"(af[mi][3]),
                          "r"(bf[ni][0]), "r"(bf[ni][1]));
                }
        }

        if (i + 1 < niter) {
            char* dst = smem + ((i + 1) & 1) * 32768;
#pragma unroll
            for (int t = 0; t < 4; t++) {
                int r = gr + (t << 5);
                uint32_t off = (uint32_t)((r << 7) + (gc << 4));
                *(uint4*)(dst + SWZ128(off)) = ra[t];
                *(uint4*)(dst + 16384 + SWZ128(off)) = rb[t];
            }
        }
        __syncthreads();
    }

    const int l4 = lid >> 2, l2 = (lid & 3) << 1;
#pragma unroll
    for (int mi = 0; mi < 4; mi++) {
#pragma unroll
        for (int ni = 0; ni < 4; ni++) {
            int rg = row0 + wr + mi * 16 + l4;
            int cg = col0 + wc + ni * 8 + l2;
            float b0 = bias[cg], b1 = bias[cg + 1];
            float2 v0 = make_float2(acc[mi][ni][0] + b0, acc[mi][ni][1] + b1);
            float2 v1 = make_float2(acc[mi][ni][2] + b0, acc[mi][ni][3] + b1);
            if (RELU) {
                v0.x = fmaxf(v0.x, 0.f); v0.y = fmaxf(v0.y, 0.f);
                v1.x = fmaxf(v1.x, 0.f); v1.y = fmaxf(v1.y, 0.f);
            }
            *(float2*)(C + (size_t)rg * N + cg) = v0;
            *(float2*)(C + (size_t)(rg + 8) * N + cg) = v1;
        }
    }
}

// ================= HMMA scores: w = (qs . ks^T)/sqrt(96), masked ================
// grid (8 k-tiles, 8 q-tiles, 64 bh), 128x128 tile, Kp=384 (niter=6)
__global__ __launch_bounds__(256)
void scores_mma(const __nv_bfloat16* __restrict__ qs,
                const __nv_bfloat16* __restrict__ ks, float* __restrict__ w)
{
    extern __shared__ char smem[];
    const uint32_t sb = smem_u32(smem);
    const int bh = blockIdx.z, b = bh >> 3;
    const int k0 = blockIdx.x << 7, q0 = blockIdx.y << 7;
    const int tid = threadIdx.x, wid = tid >> 5, lid = tid & 31;

    float* wrow = w + (size_t)bh * SS * SS;

    if (k0 > q0 + 127) {    // fully causally masked tile
        const float4 neg = make_float4(-1e9f, -1e9f, -1e9f, -1e9f);
        int c4 = (tid & 31) << 2;
        int rb = (tid >> 5) << 4;
#pragma unroll
        for (int t = 0; t < 16; t++)
            *(float4*)(wrow + (size_t)(q0 + rb + t) * SS + k0 + c4) = neg;
        return;
    }

    const int wr = (wid & 1) << 6;
    const int wc = (wid >> 1) << 5;
    const int gr = tid >> 3, gc = tid & 7;
    const int a_row = (lid & 7) + ((lid >> 3) & 1) * 8;
    const int a_kb  = (lid >> 4) * 8;
    const int b_row = (lid & 7);
    const int b_kb  = ((lid >> 3) & 1) * 8;

    float acc[4][4][4];
#pragma unroll
    for (int mi = 0; mi < 4; mi++)
#pragma unroll
        for (int ni = 0; ni < 4; ni++)
#pragma unroll
            for (int r = 0; r < 4; r++) acc[mi][ni][r] = 0.f;

    const int Kp = 384, niter = 6;
    const __nv_bfloat16* Abase = qs + ((size_t)bh * SS + q0) * Kp;
    const __nv_bfloat16* Bbase = ks + ((size_t)bh * SS + k0) * Kp;

    {
#pragma unroll
        for (int t = 0; t < 4; t++) {
            int r = gr + (t << 5);
            uint32_t off = (uint32_t)((r << 7) + (gc << 4));
            *(uint4*)(smem + SWZ128(off)) =
                *(const uint4*)(Abase + (size_t)r * Kp + (gc << 3));
            *(uint4*)(smem + 16384 + SWZ128(off)) =
                *(const uint4*)(Bbase + (size_t)r * Kp + (gc << 3));
        }
    }
    __syncthreads();

    for (int i = 0; i < niter; i++) {
        uint4 ra[4], rb[4];
        if (i + 1 < niter) {
            const __nv_bfloat16* Ag = Abase + ((i + 1) << 6);
            const __nv_bfloat16* Bg = Bbase + ((i + 1) << 6);
#pragma unroll
            for (int t = 0; t < 4; t++) {
                int r = gr + (t << 5);
                ra[t] = *(const uint4*)(Ag + (size_t)r * Kp + (gc << 3));
                rb[t] = *(const uint4*)(Bg + (size_t)r * Kp + (gc << 3));
            }
        }
        const uint32_t sA = sb + (uint32_t)((i & 1) * 32768);
        const uint32_t sB = sA + 16384;
#pragma unroll
        for (int kk = 0; kk < 4; kk++) {
            uint32_t af[4][4], bf[4][2];
#pragma unroll
            for (int mi = 0; mi < 4; mi++) {
                uint32_t off = (uint32_t)(((wr + mi * 16 + a_row) << 7) +
                                          ((kk * 16 + a_kb) << 1));
                asm volatile("ldmatrix.sync.aligned.m8n8.x4.shared.b16 {%0,%1,%2,%3}, [%4];"
                             : "=r"(af[mi][0]), "=r"(af[mi][1]), "=r"(af[mi][2]), "=r"(af[mi][3])
                             : "r"(sA + SWZ128(off)));
            }
#pragma unroll
            for (int ni = 0; ni < 4; ni++) {
                uint32_t off = (uint32_t)(((wc + ni * 8 + b_row) << 7) +
                                          ((kk * 16 + b_kb) << 1));
                asm volatile("ldmatrix.sync.aligned.m8n8.x2.shared.b16 {%0,%1}, [%2];"
                             : "=r"(bf[ni][0]), "=r"(bf[ni][1])
                             : "r"(sB + SWZ128(off)));
            }
#pragma unroll
            for (int mi = 0; mi < 4; mi++)
#pragma unroll
                for (int ni = 0; ni < 4; ni++) {
                    asm volatile(
                        "mma.sync.aligned.m16n8k16.row.col.f32.bf16.bf16.f32 "
                        "{%0,%1,%2,%3}, {%4,%5,%6,%7}, {%8,%9}, {%0,%1,%2,%3};"
                        : "+f"(acc[mi][ni][0]), "+f"(acc[mi][ni][1]),
                          "+f"(acc[mi][ni][2]), "+f"(acc[mi][ni][3])
                        : "r"(af[mi][0]), "r"(af[mi][1]), "r"(af[mi][2]), "r"(af[mi][3]),
                          "r"(bf[ni][0]), "r"(bf[ni][1]));
                }
        }
        if (i + 1 < niter) {
            char* dst = smem + ((i + 1) & 1) * 32768;
#pragma unroll
            for (int t = 0; t < 4; t++) {
                int r = gr + (t << 5);
                uint32_t off = (uint32_t)((r << 7) + (gc << 4));
                *(uint4*)(dst + SWZ128(off)) = ra[t];
                *(uint4*)(dst + 16384 + SWZ128(off)) = rb[t];
            }
        }
        __syncthreads();
    }

    const float scale = 0.10206207261596577f;  // 1/sqrt(96)
    const int l4 = lid >> 2, l2 = (lid & 3) << 1;
#pragma unroll
    for (int mi = 0; mi < 4; mi++) {
        int q1 = q0 + wr + mi * 16 + l4;
        int q2 = q1 + 8;
        bool pm1 = (g_mask[b * SS + q1] != 0);
        bool pm2 = (g_mask[b * SS + q2] != 0);
#pragma unroll
        for (int ni = 0; ni < 4; ni++) {
            int cg = k0 + wc + ni * 8 + l2;
            float2 v0, v1;
            v0.x = (pm1 || cg     > q1) ? -1e9f : acc[mi][ni][0] * scale;
            v0.y = (pm1 || cg + 1 > q1) ? -1e9f : acc[mi][ni][1] * scale;
            v1.x = (pm2 || cg     > q2) ? -1e9f : acc[mi][ni][2] * scale;
            v1.y = (pm2 || cg + 1 > q2) ? -1e9f : acc[mi][ni][3] * scale;
            *(float2*)(wrow + (size_t)q1 * SS + cg) = v0;
            *(float2*)(wrow + (size_t)q2 * SS + cg) = v1;
        }
    }
}

// ================= HMMA attnout: o = P @ V  (M=128 q, N=96 d, K'=3072) ==========
// A = g_p[bh] [1024, 2048] ([hi|lo], k-block remap hi,hi,lo)
// B = g_vt[b] + h*96 rows, [96, 3072] ([hi|lo|hi])
#define ATTN_SMEM_BYTES 57344   // 2 * (16384 A + 12288 B)

__global__ __launch_bounds__(256)
void attnout_mma(const __nv_bfloat16* __restrict__ P,
                 const __nv_bfloat16* __restrict__ Vt, float* __restrict__ o)
{
    extern __shared__ char smem[];
    const uint32_t sb = smem_u32(smem);
    const int bh = blockIdx.y, b = bh >> 3, h = bh & 7;
    const int q0 = blockIdx.x << 7;
    const int tid = threadIdx.x, wid = tid >> 5, lid = tid & 31;
    const int wr = (wid & 1) << 6;
    const int wc = (wid >> 1) * 24;
    const int gr = tid >> 3, gc = tid & 7;
    const int a_row = (lid & 7) + ((lid >> 3) & 1) * 8;
    const int a_kb  = (lid >> 4) * 8;
    const int b_row = (lid & 7);
    const int b_kb  = ((lid >> 3) & 1) * 8;

    const __nv_bfloat16* Abase = P + ((size_t)bh * SS + q0) * 2048;
    const __nv_bfloat16* Bbase = Vt + ((size_t)b * DD + h * DKK) * 3072;

    float acc[4][3][4];
#pragma unroll
    for (int mi = 0; mi < 4; mi++)
#pragma unroll
        for (int ni = 0; ni < 3; ni++)
#pragma unroll
            for (int r = 0; r < 4; r++) acc[mi][ni][r] = 0.f;

    const int niter = 48;
    // A k-offset remap: blocks 0-15 -> hi, 16-31 -> hi, 32-47 -> lo plane
#define AOFF(i) (((i) < 32) ? (((i) & 15) << 6) : (1024 + (((i) - 32) << 6)))

    {   // preload stage 0
#pragma unroll
        for (int t = 0; t < 4; t++) {
            int r = gr + (t << 5);
            uint32_t off = (uint32_t)((r << 7) + (gc << 4));
            *(uint4*)(smem + SWZ128(off)) =
                *(const uint4*)(Abase + (size_t)r * 2048 + AOFF(0) + (gc << 3));
        }
#pragma unroll
        for (int t = 0; t < 3; t++) {
            int r = gr + (t << 5);
            uint32_t off = (uint32_t)((r << 7) + (gc << 4));
            *(uint4*)(smem + 16384 + SWZ128(off)) =
                *(const uint4*)(Bbase + (size_t)r * 3072 + (gc << 3));
        }
    }
    __syncthreads();

    for (int i = 0; i < niter; i++) {
        uint4 ra[4], rb[3];
        if (i + 1 < niter) {
            int ao = AOFF(i + 1), bo = (i + 1) << 6;
#pragma unroll
            for (int t = 0; t < 4; t++) {
                int r = gr + (t << 5);
                ra[t] = *(const uint4*)(Abase + (size_t)r * 2048 + ao + (gc << 3));
            }
#pragma unroll
            for (int t = 0; t < 3; t++) {
                int r = gr + (t << 5);
                rb[t] = *(const uint4*)(Bbase + (size_t)r * 3072 + bo + (gc << 3));
            }
        }
        const uint32_t sA = sb + (uint32_t)((i & 1) * 28672);
        const uint32_t sB = sA + 16384;
#pragma unroll
        for (int kk = 0; kk < 4; kk++) {
            uint32_t af[4][4], bf[3][2];
#pragma unroll
            for (int mi = 0; mi < 4; mi++) {
                uint32_t off = (uint32_t)(((wr + mi * 16 + a_row) << 7) +
                                          ((kk * 16 + a_kb) << 1));
                asm volatile("ldmatrix.sync.aligned.m8n8.x4.shared.b16 {%0,%1,%2,%3}, [%4];"
                             : "=r"(af[mi][0]), "=r"(af[mi][1]), "=r"(af[mi][2]), "=r"(af[mi][3])
                             : "r"(sA + SWZ128(off)));
            }
#pragma unroll
            for (int ni = 0; ni < 3; ni++) {
                uint32_t off = (uint32_t)(((wc + ni * 8 + b_row) << 7) +
                                          ((kk * 16 + b_kb) << 1));
                asm volatile("ldmatrix.sync.aligned.m8n8.x2.shared.b16 {%0,%1}, [%2];"
                             : "=r"(bf[ni][0]), "=r"(bf[ni][1])
                             : "r"(sB + SWZ128(off)));
            }
#pragma unroll
            for (int mi = 0; mi < 4; mi++)
#pragma unroll
                for (int ni = 0; ni < 3; ni++) {
                    asm volatile(
                        "mma.sync.aligned.m16n8k16.row.col.f32.bf16.bf16.f32 "
                        "{%0,%1,%2,%3}, {%4,%5,%6,%7}, {%8,%9}, {%0,%1,%2,%3};"
                        : "+f"(acc[mi][ni][0]), "+f"(acc[mi][ni][1]),
                          "+f"(acc[mi][ni][2]), "+f"(acc[mi][ni][3])
                        : "r"(af[mi][0]), "r"(af[mi][1]), "r"(af[mi][2]), "r"(af[mi][3]),
                          "r"(bf[ni][0]), "r"(bf[ni][1]));
                }
        }
        if (i + 1 < niter) {
            char* dst = smem + ((i + 1) & 1) * 28672;
#pragma unroll
            for (int t = 0; t < 4; t++) {
                int r = gr + (t << 5);
                uint32_t off = (uint32_t)((r << 7) + (gc << 4));
                *(uint4*)(dst + SWZ128(off)) = ra[t];
            }
#pragma unroll
            for (int t = 0; t < 3; t++) {
                int r = gr + (t << 5);
                uint32_t off = (uint32_t)((r << 7) + (gc << 4));
                *(uint4*)(dst + 16384 + SWZ128(off)) = rb[t];
            }
        }
        __syncthreads();
    }
#undef AOFF

    const int l4 = lid >> 2, l2 = (lid & 3) << 1;
#pragma unroll
    for (int mi = 0; mi < 4; mi++) {
#pragma unroll
        for (int ni = 0; ni < 3; ni++) {
            int rg = b * SS + q0 + wr + mi * 16 + l4;
            int cg = h * DKK + wc + ni * 8 + l2;
            *(float2*)(o + (size_t)rg * DD + cg) =
                make_float2(acc[mi][ni][0], acc[mi][ni][1]);
            *(float2*)(o + (size_t)(rg + 8) * DD + cg) =
                make_float2(acc[mi][ni][2], acc[mi][ni][3]);
        }
    }
}

// ================= mask canonicalization ========================================
__global__ void detect_mask_kernel(const unsigned char* __restrict__ m)
{
    __shared__ int s_big, s_mis;
    if (threadIdx.x == 0) { s_big = 0; s_mis = 0; }
    __syncthreads();
    int big = 0, mis = 0;
    for (int i = threadIdx.x; i < NR; i += blockDim.x) {
        unsigned char v = m[i];
        if (v > 1) big = 1;
        if ((i & 3) != 0 && v != 0) mis = 1;
    }
    if (big) atomicOr(&s_big, 1);
    if (mis) atomicOr(&s_mis, 1);
    __syncthreads();
    if (threadIdx.x == 0) { g_flags[0] = s_big; g_flags[1] = s_mis; }
}

__global__ void convert_mask_kernel(const void* __restrict__ m)
{
    int i = blockIdx.x * blockDim.x + threadIdx.x;
    bool word32 = (g_flags[0] != 0) || (g_flags[1] == 0);
    unsigned char out;
    if (word32) out = (((const unsigned int*)m)[i] != 0u) ? 1 : 0;
    else        out = (((const unsigned char*)m)[i] != 0) ? 1 : 0;
    g_mask[i] = out;
}

// ================= column softmax stats =========================================
__global__ __launch_bounds__(256)
void colstats_kernel(const float* __restrict__ w, float* __restrict__ cm,
                     float* __restrict__ cs)
{
    const int bh = blockIdx.y;
    const int k  = (blockIdx.x << 8) + threadIdx.x;
    const float* wb = w + (size_t)bh * SS * SS + k;
    float m = __int_as_float(0xff800000);
    float s = 0.f;
    for (int qq = 0; qq < SS; qq++) {
        float v = wb[(size_t)qq * SS];
        if (v > m) { s = s * __expf(m - v) + 1.0f; m = v; }
        else       { s += __expf(v - m); }
    }
    cm[bh * SS + k] = m;
    cs[bh * SS + k] = s;
}

// ================= residual add + layernorm =====================================
__global__ __launch_bounds__(256)
void addln_kernel(const float* __restrict__ a, const float* __restrict__ r,
                  const float* __restrict__ g, const float* __restrict__ beta,
                  float* __restrict__ out)
{
    const int row = blockIdx.x;
    const int tid = threadIdx.x;
    const float* ap = a + (size_t)row * DD;
    const float* rp = r + (size_t)row * DD;

    float v[3];
    float sum = 0.f, sq = 0.f;
#pragma unroll
    for (int i = 0; i < 3; i++) {
        int c = tid + (i << 8);
        v[i] = ap[c] + rp[c];
        sum += v[i];
        sq  += v[i] * v[i];
    }
#pragma unroll
    for (int off = 16; off > 0; off >>= 1) {
        sum += __shfl_xor_sync(0xffffffffu, sum, off);
        sq  += __shfl_xor_sync(0xffffffffu, sq,  off);
    }
    __shared__ float s1[8], s2[8];
    int warp = tid >> 5, lane = tid & 31;
    if (lane == 0) { s1[warp] = sum; s2[warp] = sq; }
    __syncthreads();
    if (warp == 0) {
        float aa = (lane < 8) ? s1[lane] : 0.f;
        float bb = (lane < 8) ? s2[lane] : 0.f;
#pragma unroll
        for (int off = 4; off > 0; off >>= 1) {
            aa += __shfl_xor_sync(0xffffffffu, aa, off);
            bb += __shfl_xor_sync(0xffffffffu, bb, off);
        }
        if (lane == 0) { s1[0] = aa; s2[0] = bb; }
    }
    __syncthreads();
    const float invD = 1.0f / 768.0f;
    float mean = s1[0] * invD;
    float var  = s2[0] * invD - mean * mean;
    float inv  = rsqrtf(var + 1e-5f);
#pragma unroll
    for (int i = 0; i < 3; i++) {
        int c = tid + (i << 8);
        out[(size_t)row * DD + c] = (v[i] - mean) * inv * g[c] + beta[c];
    }
}

// ================= host side ====================================================
static void run_mha(const float* xin,
                    const float* Wq, const float* bq,
                    const float* Wv, const float* bv,
                    const float* g, const float* beta,
                    __nv_bfloat16* a2, __nv_bfloat16* b2t,
                    __nv_bfloat16* qs, __nv_bfloat16* ks,
                    __nv_bfloat16* pbuf, __nv_bfloat16* vt,
                    float* q, float* kv, float* w, float* cm, float* cs,
                    float* o, float* xout)
{
    split_a_kernel<<<NR * DD / 256, 256>>>(xin, a2, DD);
    split_wt_kernel<<<dim3(DD / 32, DD / 32), dim3(32, 8)>>>(Wq, b2t, DD, DD);
    mma_gemm<false><<<dim3(DD / 128, NR / 128), 256, GEMM_SMEM_BYTES>>>(a2, b2t, bq, q, DD, 3 * DD);
    split_wt_kernel<<<dim3(DD / 32, DD / 32), dim3(32, 8)>>>(Wv, b2t, DD, DD);
    mma_gemm<false><<<dim3(DD / 128, NR / 128), 256, GEMM_SMEM_BYTES>>>(a2, b2t, bv, kv, DD, 3 * DD);

    split_qk_kernel<0><<<NR * 1024 / 256, 256>>>(q,  qs);
    split_qk_kernel<1><<<NR * 1024 / 256, 256>>>(kv, ks);
    scores_mma<<<dim3(SS / 128, SS / 128, NBH), 256, GEMM_SMEM_BYTES>>>(qs, ks, w);
    colstats_kernel<<<dim3(SS / 256, NBH), 256>>>(w, cm, cs);
    psplit_kernel<<<NBH * SS, 256>>>(w, cm, cs, pbuf);
    split_vt_kernel<<<dim3(DD / 32, SS / 32, BB), dim3(32, 8)>>>(kv, vt);
    attnout_mma<<<dim3(SS / 128, NBH), 256, ATTN_SMEM_BYTES>>>(pbuf, vt, o);
    addln_kernel<<<NR, 256>>>(o, xin, g, beta, xout);
}

extern "C" void kernel_launch(void* const* d_in, const int* in_sizes, int n_in,
                              void* d_out, int out_size)
{
    (void)in_sizes; (void)n_in; (void)out_size;

    const float* x     = (const float*)d_in[0];
    const void*  amraw = d_in[1];
    const float* a1_Wq = (const float*)d_in[2];
    const float* a1_bq = (const float*)d_in[3];
    const float* a1_Wv = (const float*)d_in[4];
    const float* a1_bv = (const float*)d_in[5];
    const float* a1_g  = (const float*)d_in[6];
    const float* a1_b  = (const float*)d_in[7];
    const float* a2_Wq = (const float*)d_in[8];
    const float* a2_bq = (const float*)d_in[9];
    const float* a2_Wv = (const float*)d_in[10];
    const float* a2_bv = (const float*)d_in[11];
    const float* a2_g  = (const float*)d_in[12];
    const float* a2_b  = (const float*)d_in[13];
    const float* f_W1  = (const float*)d_in[14];
    const float* f_b1  = (const float*)d_in[15];
    const float* f_W2  = (const float*)d_in[16];
    const float* f_b2  = (const float*)d_in[17];
    const float* f_g   = (const float*)d_in[18];
    const float* f_b   = (const float*)d_in[19];
    float* out = (float*)d_out;

    float *q, *kv, *w, *cm, *cs, *o, *x1, *x2, *hbuf;
    __nv_bfloat16 *a2buf, *b2t, *qs, *ks, *pbuf, *vt;
    cudaGetSymbolAddress((void**)&q,     g_q);
    cudaGetSymbolAddress((void**)&kv,    g_kv);
    cudaGetSymbolAddress((void**)&w,     g_w);
    cudaGetSymbolAddress((void**)&cm,    g_cm);
    cudaGetSymbolAddress((void**)&cs,    g_cs);
    cudaGetSymbolAddress((void**)&o,     g_o);
    cudaGetSymbolAddress((void**)&x1,    g_x1);
    cudaGetSymbolAddress((void**)&x2,    g_x2);
    cudaGetSymbolAddress((void**)&hbuf,  g_h);
    cudaGetSymbolAddress((void**)&a2buf, g_a2);
    cudaGetSymbolAddress((void**)&b2t,   g_b2t);
    cudaGetSymbolAddress((void**)&qs,    g_qs);
    cudaGetSymbolAddress((void**)&ks,    g_ks);
    cudaGetSymbolAddress((void**)&pbuf,  g_p);
    cudaGetSymbolAddress((void**)&vt,    g_vt);

    cudaFuncSetAttribute(mma_gemm<false>, cudaFuncAttributeMaxDynamicSharedMemorySize, GEMM_SMEM_BYTES);
    cudaFuncSetAttribute(mma_gemm<true >, cudaFuncAttributeMaxDynamicSharedMemorySize, GEMM_SMEM_BYTES);
    cudaFuncSetAttribute(scores_mma,      cudaFuncAttributeMaxDynamicSharedMemorySize, GEMM_SMEM_BYTES);
    cudaFuncSetAttribute(attnout_mma,     cudaFuncAttributeMaxDynamicSharedMemorySize, ATTN_SMEM_BYTES);

    // canonicalize the attention mask (robust to uint8 / int32 / float32 delivery)
    detect_mask_kernel<<<1, 256>>>((const unsigned char*)amraw);
    convert_mask_kernel<<<NR / 256, 256>>>(amraw);

    // layer 1 + layer 2 MHA
    run_mha(x,  a1_Wq, a1_bq, a1_Wv, a1_bv, a1_g, a1_b,
            a2buf, b2t, qs, ks, pbuf, vt, q, kv, w, cm, cs, o, x1);
    run_mha(x1, a2_Wq, a2_bq, a2_Wv, a2_bv, a2_g, a2_b,
            a2buf, b2t, qs, ks, pbuf, vt, q, kv, w, cm, cs, o, x2);

    // FFN
    split_a_kernel<<<NR * DD / 256, 256>>>(x2, a2buf, DD);
    split_wt_kernel<<<dim3(FFD / 32, DD / 32), dim3(32, 8)>>>(f_W1, b2t, DD, FFD);
    mma_gemm<true ><<<dim3(FFD / 128, NR / 128), 256, GEMM_SMEM_BYTES>>>(a2buf, b2t, f_b1, hbuf, FFD, 3 * DD);
    split_a_kernel<<<NR * FFD / 256, 256>>>(hbuf, a2buf, FFD);
    split_wt_kernel<<<dim3(DD / 32, FFD / 32), dim3(32, 8)>>>(f_W2, b2t, FFD, DD);
    mma_gemm<false><<<dim3(DD / 128, NR / 128), 256, GEMM_SMEM_BYTES>>>(a2buf, b2t, f_b2, o, DD, 3 * FFD);
    addln_kernel<<<NR, 256>>>(o, x2, f_g, f_b, out);
}

// round 15
// speedup vs baseline: 1.9055x; 1.1733x over previous
#include <cuda_runtime.h>
#include <cuda_bf16.h>
#include <cstdint>

#define BB   8
#define SS   1024
#define DD   768
#define HH   8
#define DKK  96
#define FFD  1024
#define NR   (BB * SS)        // 8192 rows
#define NBH  (BB * HH)        // 64 (b,h) pairs

// ---------------- scratch (static device globals; no allocation) ----------------
__device__ float g_q [NR * DD];
__device__ float g_kv[NR * DD];
__device__ float g_w [(size_t)NBH * SS * SS];   // score matrix (fp32); masked tiles unwritten
__device__ float g_cm [NBH * SS];
__device__ float g_ics[NBH * SS];
__device__ float g_pm [NBH * 8 * SS];           // per-(bh,qtile,k) partial max
__device__ float g_ps [NBH * 8 * SS];           // per-(bh,qtile,k) partial sumexp
__device__ float g_o [NR * DD];
__device__ float g_x1[NR * DD];
__device__ float g_x2[NR * DD];
__device__ float g_h [NR * FFD];
__device__ unsigned char g_mask[NR];
__device__ int g_flags[2];
__device__ __nv_bfloat16 g_a2 [(size_t)NR * 3 * 1024];    // split A  (dense GEMMs)
__device__ __nv_bfloat16 g_b2t[(size_t)1024 * 3 * 1024];  // split W^T (dense GEMMs)
__device__ __nv_bfloat16 g_qs [(size_t)NBH * SS * 384];   // q  split [hi|hi|lo], DK pad 128
__device__ __nv_bfloat16 g_ks [(size_t)NBH * SS * 384];   // kv split [hi|lo|hi], DK pad 128
__device__ __nv_bfloat16 g_vt [(size_t)BB * DD * 2048];   // V^T split [hi|lo] per batch

#define SWZ128(o) ((o) ^ (((o) >> 3) & 0x70))

__device__ __forceinline__ uint32_t smem_u32(const void* p) {
    uint32_t a;
    asm("{ .reg .u64 t; cvta.to.shared.u64 t, %1; cvt.u32.u64 %0, t; }" : "=r"(a) : "l"(p));
    return a;
}

// ================= bf16 split conversions (dense GEMM path) =====================
__global__ void split_a_kernel(const float* __restrict__ X,
                               __nv_bfloat16* __restrict__ A2, int K)
{
    int idx = blockIdx.x * 256 + threadIdx.x;
    int r = idx / K, k = idx - r * K;
    float v = X[idx];
    __nv_bfloat16 h = __float2bfloat16(v);
    __nv_bfloat16 l = __float2bfloat16(v - __bfloat162float(h));
    __nv_bfloat16* row = A2 + (size_t)r * 3 * K;
    row[k] = h; row[K + k] = h; row[2 * K + k] = l;
}

__global__ void split_wt_kernel(const float* __restrict__ W,
                                __nv_bfloat16* __restrict__ Bt, int K, int N)
{
    __shared__ float t[32][33];
    int nb = blockIdx.x * 32, kb = blockIdx.y * 32;
    int x = threadIdx.x, y = threadIdx.y;          // 32 x 8
#pragma unroll
    for (int yy = 0; yy < 32; yy += 8)
        t[y + yy][x] = W[(size_t)(kb + y + yy) * N + nb + x];
    __syncthreads();
    const size_t K3 = 3 * (size_t)K;
#pragma unroll
    for (int yy = 0; yy < 32; yy += 8) {
        int n = nb + y + yy;
        int k = kb + x;
        float v = t[x][y + yy];
        __nv_bfloat16 h = __float2bfloat16(v);
        __nv_bfloat16 l = __float2bfloat16(v - __bfloat162float(h));
        Bt[(size_t)n * K3 + k] = h;
        Bt[(size_t)n * K3 + K + k] = l;
        Bt[(size_t)n * K3 + 2 * K + k] = h;
    }
}

// ================= attention split conversions ==================================
template <int PAIR>
__global__ void split_qk_kernel(const float* __restrict__ src,
                                __nv_bfloat16* __restrict__ dst)
{
    int idx = blockIdx.x * 256 + threadIdx.x;       // over 8192*1024
    int row = idx >> 10, cp = idx & 1023;
    int h = cp >> 7, dd = cp & 127;
    float v = (dd < DKK) ? src[(size_t)row * DD + h * DKK + dd] : 0.f;
    __nv_bfloat16 hi = __float2bfloat16(v);
    __nv_bfloat16 lo = __float2bfloat16(v - __bfloat162float(hi));
    int b = row >> 10, s = row & 1023;
    __nv_bfloat16* out = dst + ((size_t)(b * HH + h) * SS + s) * 384 + dd;
    if (PAIR == 0) { out[0] = hi; out[128] = hi; out[256] = lo; }
    else           { out[0] = hi; out[128] = lo; out[256] = hi; }
}

// kv per batch [1024 k, 768 n] -> vt[b][n][2048] planes [hi|lo]
__global__ void split_vt_kernel(const float* __restrict__ kv,
                                __nv_bfloat16* __restrict__ vt)
{
    __shared__ float t[32][33];
    int b = blockIdx.z;
    const float* W = kv + (size_t)b * SS * DD;
    __nv_bfloat16* Bt = vt + (size_t)b * DD * 2048;
    int nb = blockIdx.x * 32, kb = blockIdx.y * 32;
    int x = threadIdx.x, y = threadIdx.y;
#pragma unroll
    for (int yy = 0; yy < 32; yy += 8)
        t[y + yy][x] = W[(size_t)(kb + y + yy) * DD + nb + x];
    __syncthreads();
#pragma unroll
    for (int yy = 0; yy < 32; yy += 8) {
        int n = nb + y + yy;
        int k = kb + x;
        float v = t[x][y + yy];
        __nv_bfloat16 h = __float2bfloat16(v);
        __nv_bfloat16 l = __float2bfloat16(v - __bfloat162float(h));
        Bt[(size_t)n * 2048 + k] = h;
        Bt[(size_t)n * 2048 + 1024 + k] = l;
    }
}

// ================= HMMA dense GEMM (validated R9) ===============================
#define GEMM_SMEM_BYTES 65536

template <bool RELU>
__global__ __launch_bounds__(256)
void mma_gemm(const __nv_bfloat16* __restrict__ A2, const __nv_bfloat16* __restrict__ Bt,
              const float* __restrict__ bias, float* __restrict__ C, int N, int Kp)
{
    extern __shared__ char smem[];
    const uint32_t sb = smem_u32(smem);
    const int tid = threadIdx.x, wid = tid >> 5, lid = tid & 31;
    const int row0 = blockIdx.y << 7, col0 = blockIdx.x << 7;
    const int wr = (wid & 1) << 6;
    const int wc = (wid >> 1) << 5;

    const int gr = tid >> 3;
    const int gc = tid & 7;

    const int a_row = (lid & 7) + ((lid >> 3) & 1) * 8;
    const int a_kb  = (lid >> 4) * 8;
    const int b_row = (lid & 7);
    const int b_kb  = ((lid >> 3) & 1) * 8;

    float acc[4][4][4];
#pragma unroll
    for (int mi = 0; mi < 4; mi++)
#pragma unroll
        for (int ni = 0; ni < 4; ni++)
#pragma unroll
            for (int r = 0; r < 4; r++) acc[mi][ni][r] = 0.f;

    const int niter = Kp >> 6;

    {
        const __nv_bfloat16* Ag = A2 + (size_t)row0 * Kp;
        const __nv_bfloat16* Bg = Bt + (size_t)col0 * Kp;
#pragma unroll
        for (int t = 0; t < 4; t++) {
            int r = gr + (t << 5);
            uint32_t off = (uint32_t)((r << 7) + (gc << 4));
            *(uint4*)(smem + SWZ128(off)) =
                *(const uint4*)(Ag + (size_t)r * Kp + (gc << 3));
            *(uint4*)(smem + 16384 + SWZ128(off)) =
                *(const uint4*)(Bg + (size_t)r * Kp + (gc << 3));
        }
    }
    __syncthreads();

    for (int i = 0; i < niter; i++) {
        uint4 ra[4], rb[4];
        if (i + 1 < niter) {
            const __nv_bfloat16* Ag = A2 + (size_t)row0 * Kp + ((i + 1) << 6);
            const __nv_bfloat16* Bg = Bt + (size_t)col0 * Kp + ((i + 1) << 6);
#pragma unroll
            for (int t = 0; t < 4; t++) {
                int r = gr + (t << 5);
                ra[t] = *(const uint4*)(Ag + (size_t)r * Kp + (gc << 3));
                rb[t] = *(const uint4*)(Bg + (size_t)r * Kp + (gc << 3));
            }
        }

        const uint32_t sA = sb + (uint32_t)((i & 1) * 32768);
        const uint32_t sB = sA + 16384;
#pragma unroll
        for (int kk = 0; kk < 4; kk++) {
            uint32_t af[4][4], bf[4][2];
#pragma unroll
            for (int mi = 0; mi < 4; mi++) {
                uint32_t off = (uint32_t)(((wr + mi * 16 + a_row) << 7) +
                                          ((kk * 16 + a_kb) << 1));
                asm volatile("ldmatrix.sync.aligned.m8n8.x4.shared.b16 {%0,%1,%2,%3}, [%4];"
                             : "=r"(af[mi][0]), "=r"(af[mi][1]), "=r"(af[mi][2]), "=r"(af[mi][3])
                             : "r"(sA + SWZ128(off)));
            }
#pragma unroll
            for (int ni = 0; ni < 4; ni++) {
                uint32_t off = (uint32_t)(((wc + ni * 8 + b_row) << 7) +
                                          ((kk * 16 + b_kb) << 1));
                asm volatile("ldmatrix.sync.aligned.m8n8.x2.shared.b16 {%0,%1}, [%2];"
                             : "=r"(bf[ni][0]), "=r"(bf[ni][1])
                             : "r"(sB + SWZ128(off)));
            }
#pragma unroll
            for (int mi = 0; mi < 4; mi++)
#pragma unroll
                for (int ni = 0; ni < 4; ni++) {
                    asm volatile(
                        "mma.sync.aligned.m16n8k16.row.col.f32.bf16.bf16.f32 "
                        "{%0,%1,%2,%3}, {%4,%5,%6,%7}, {%8,%9}, {%0,%1,%2,%3};"
                        : "+f"(acc[mi][ni][0]), "+f"(acc[mi][ni][1]),
                          "+f"(acc[mi][ni][2]), "+f"(acc[mi][ni][3])
                        : "r"(af[mi][0]), "r"(af[mi][1]), "r"(af[mi][2]), "r"(af[mi][3]),
                          "r"(bf[ni][0]), "r"(bf[ni][1]));
                }
        }

        if (i + 1 < niter) {
            char* dst = smem + ((i + 1) & 1) * 32768;
#pragma unroll
            for (int t = 0; t < 4; t++) {
                int r = gr + (t << 5);
                uint32_t off = (uint32_t)((r << 7) + (gc << 4));
                *(uint4*)(dst + SWZ128(off)) = ra[t];
                *(uint4*)(dst + 16384 + SWZ128(off)) = rb[t];
            }
        }
        __syncthreads();
    }

    const int l4 = lid >> 2, l2 = (lid & 3) << 1;
#pragma unroll
    for (int mi = 0; mi < 4; mi++) {
#pragma unroll
        for (int ni = 0; ni < 4; ni++) {
            int rg = row0 + wr + mi * 16 + l4;
            int cg = col0 + wc + ni * 8 + l2;
            float b0 = bias[cg], b1 = bias[cg + 1];
            float2 v0 = make_float2(acc[mi][ni][0] + b0, acc[mi][ni][1] + b1);
            float2 v1 = make_float2(acc[mi][ni][2] + b0, acc[mi][ni][3] + b1);
            if (RELU) {
                v0.x = fmaxf(v0.x, 0.f); v0.y = fmaxf(v0.y, 0.f);
                v1.x = fmaxf(v1.x, 0.f); v1.y = fmaxf(v1.y, 0.f);
            }
            *(float2*)(C + (size_t)rg * N + cg) = v0;
            *(float2*)(C + (size_t)(rg + 8) * N + cg) = v1;
        }
    }
}

// ================= HMMA scores + in-epilogue column stats =======================
// grid (8 k-tiles, 8 q-tiles, 64 bh), 128x128 tile, Kp=384 (niter=6)
// Writes w ONLY for processed tiles; per-tile column partials (max,sumexp) always.
__global__ __launch_bounds__(256)
void scores_mma(const __nv_bfloat16* __restrict__ qs,
                const __nv_bfloat16* __restrict__ ks, float* __restrict__ w,
                float* __restrict__ pm, float* __restrict__ ps)
{
    extern __shared__ char smem[];
    const uint32_t sb = smem_u32(smem);
    const int bh = blockIdx.z, b = bh >> 3;
    const int k0 = blockIdx.x << 7, q0 = blockIdx.y << 7;
    const int qt = q0 >> 7;
    const int tid = threadIdx.x, wid = tid >> 5, lid = tid & 31;

    if (k0 > q0 + 127) {    // fully causally masked tile: analytic partial only
        if (tid < 128) {
            size_t off = (((size_t)bh * 8 + qt) << 10) + k0 + tid;
            pm[off] = -1e9f;
            ps[off] = 128.f;
        }
        return;
    }

    float* wrow = w + (size_t)bh * SS * SS;
    const int wr = (wid & 1) << 6;
    const int wc = (wid >> 1) << 5;
    const int gr = tid >> 3, gc = tid & 7;
    const int a_row = (lid & 7) + ((lid >> 3) & 1) * 8;
    const int a_kb  = (lid >> 4) * 8;
    const int b_row = (lid & 7);
    const int b_kb  = ((lid >> 3) & 1) * 8;

    float acc[4][4][4];
#pragma unroll
    for (int mi = 0; mi < 4; mi++)
#pragma unroll
        for (int ni = 0; ni < 4; ni++)
#pragma unroll
            for (int r = 0; r < 4; r++) acc[mi][ni][r] = 0.f;

    const int Kp = 384, niter = 6;
    const __nv_bfloat16* Abase = qs + ((size_t)bh * SS + q0) * Kp;
    const __nv_bfloat16* Bbase = ks + ((size_t)bh * SS + k0) * Kp;

    {
#pragma unroll
        for (int t = 0; t < 4; t++) {
            int r = gr + (t << 5);
            uint32_t off = (uint32_t)((r << 7) + (gc << 4));
            *(uint4*)(smem + SWZ128(off)) =
                *(const uint4*)(Abase + (size_t)r * Kp + (gc << 3));
            *(uint4*)(smem + 16384 + SWZ128(off)) =
                *(const uint4*)(Bbase + (size_t)r * Kp + (gc << 3));
        }
    }
    __syncthreads();

    for (int i = 0; i < niter; i++) {
        uint4 ra[4], rb[4];
        if (i + 1 < niter) {
            const __nv_bfloat16* Ag = Abase + ((i + 1) << 6);
            const __nv_bfloat16* Bg = Bbase + ((i + 1) << 6);
#pragma unroll
            for (int t = 0; t < 4; t++) {
                int r = gr + (t << 5);
                ra[t] = *(const uint4*)(Ag + (size_t)r * Kp + (gc << 3));
                rb[t] = *(const uint4*)(Bg + (size_t)r * Kp + (gc << 3));
            }
        }
        const uint32_t sA = sb + (uint32_t)((i & 1) * 32768);
        const uint32_t sB = sA + 16384;
#pragma unroll
        for (int kk = 0; kk < 4; kk++) {
            uint32_t af[4][4], bf[4][2];
#pragma unroll
            for (int mi = 0; mi < 4; mi++) {
                uint32_t off = (uint32_t)(((wr + mi * 16 + a_row) << 7) +
                                          ((kk * 16 + a_kb) << 1));
                asm volatile("ldmatrix.sync.aligned.m8n8.x4.shared.b16 {%0,%1,%2,%3}, [%4];"
                             : "=r"(af[mi][0]), "=r"(af[mi][1]), "=r"(af[mi][2]), "=r"(af[mi][3])
                             : "r"(sA + SWZ128(off)));
            }
#pragma unroll
            for (int ni = 0; ni < 4; ni++) {
                uint32_t off = (uint32_t)(((wc + ni * 8 + b_row) << 7) +
                                          ((kk * 16 + b_kb) << 1));
                asm volatile("ldmatrix.sync.aligned.m8n8.x2.shared.b16 {%0,%1}, [%2];"
                             : "=r"(bf[ni][0]), "=r"(bf[ni][1])
                             : "r"(sB + SWZ128(off)));
            }
#pragma unroll
            for (int mi = 0; mi < 4; mi++)
#pragma unroll
                for (int ni = 0; ni < 4; ni++) {
                    asm volatile(
                        "mma.sync.aligned.m16n8k16.row.col.f32.bf16.bf16.f32 "
                        "{%0,%1,%2,%3}, {%4,%5,%6,%7}, {%8,%9}, {%0,%1,%2,%3};"
                        : "+f"(acc[mi][ni][0]), "+f"(acc[mi][ni][1]),
                          "+f"(acc[mi][ni][2]), "+f"(acc[mi][ni][3])
                        : "r"(af[mi][0]), "r"(af[mi][1]), "r"(af[mi][2]), "r"(af[mi][3]),
                          "r"(bf[ni][0]), "r"(bf[ni][1]));
                }
        }
        if (i + 1 < niter) {
            char* dst = smem + ((i + 1) & 1) * 32768;
#pragma unroll
            for (int t = 0; t < 4; t++) {
                int r = gr + (t << 5);
                uint32_t off = (uint32_t)((r << 7) + (gc << 4));
                *(uint4*)(dst + SWZ128(off)) = ra[t];
                *(uint4*)(dst + 16384 + SWZ128(off)) = rb[t];
            }
        }
        __syncthreads();
    }

    // ---- epilogue: mask + scale, write w, keep masked values in acc ----
    const float scale = 0.10206207261596577f;  // 1/sqrt(96)
    const int l4 = lid >> 2, l2 = (lid & 3) << 1;
#pragma unroll
    for (int mi = 0; mi < 4; mi++) {
        int q1 = q0 + wr + mi * 16 + l4;
        int q2 = q1 + 8;
        bool pm1 = (g_mask[b * SS + q1] != 0);
        bool pm2 = (g_mask[b * SS + q2] != 0);
#pragma unroll
        for (int ni = 0; ni < 4; ni++) {
            int cg = k0 + wc + ni * 8 + l2;
            float v00 = (pm1 || cg     > q1) ? -1e9f : acc[mi][ni][0] * scale;
            float v01 = (pm1 || cg + 1 > q1) ? -1e9f : acc[mi][ni][1] * scale;
            float v10 = (pm2 || cg     > q2) ? -1e9f : acc[mi][ni][2] * scale;
            float v11 = (pm2 || cg + 1 > q2) ? -1e9f : acc[mi][ni][3] * scale;
            *(float2*)(wrow + (size_t)q1 * SS + cg) = make_float2(v00, v01);
            *(float2*)(wrow + (size_t)q2 * SS + cg) = make_float2(v10, v11);
            acc[mi][ni][0] = v00; acc[mi][ni][1] = v01;
            acc[mi][ni][2] = v10; acc[mi][ni][3] = v11;
        }
    }

    // ---- column stats: 8 values per (ni,par) per thread, reduce over l4 lanes ----
    float* msm = (float*)smem;          // [2][128]
    float* ssm = msm + 256;
    float mcol[4][2], scol[4][2];
#pragma unroll
    for (int ni = 0; ni < 4; ni++) {
#pragma unroll
        for (int par = 0; par < 2; par++) {
            float m = acc[0][ni][par];
#pragma unroll
            for (int mi = 1; mi < 4; mi++) m = fmaxf(m, acc[mi][ni][par]);
#pragma unroll
            for (int mi = 0; mi < 4; mi++) m = fmaxf(m, acc[mi][ni][2 + par]);
            m = fmaxf(m, __shfl_xor_sync(0xffffffffu, m, 4));
            m = fmaxf(m, __shfl_xor_sync(0xffffffffu, m, 8));
            m = fmaxf(m, __shfl_xor_sync(0xffffffffu, m, 16));
            float s = 0.f;
#pragma unroll
            for (int mi = 0; mi < 4; mi++) {
                s += __expf(acc[mi][ni][par] - m);
                s += __expf(acc[mi][ni][2 + par] - m);
            }
            s += __shfl_xor_sync(0xffffffffu, s, 4);
            s += __shfl_xor_sync(0xffffffffu, s, 8);
            s += __shfl_xor_sync(0xffffffffu, s, 16);
            mcol[ni][par] = m;
            scol[ni][par] = s;
        }
    }
    if (l4 == 0) {
#pragma unroll
        for (int ni = 0; ni < 4; ni++)
#pragma unroll
            for (int par = 0; par < 2; par++) {
                int col = wc + ni * 8 + l2 + par;
                msm[(wid & 1) * 128 + col] = mcol[ni][par];
                ssm[(wid & 1) * 128 + col] = scol[ni][par];
            }
    }
    __syncthreads();
    if (tid < 128) {
        float m0 = msm[tid], m1 = msm[128 + tid];
        float s0 = ssm[tid], s1 = ssm[128 + tid];
        float m = fmaxf(m0, m1);
        float s = s0 * __expf(m0 - m) + s1 * __expf(m1 - m);
        size_t off = (((size_t)bh * 8 + qt) << 10) + k0 + tid;
        pm[off] = m;
        ps[off] = s;
    }
}

// ================= merge per-qtile partials into cm / ics =======================
__global__ void merge_stats(const float* __restrict__ pm, const float* __restrict__ ps,
                            float* __restrict__ cm, float* __restrict__ ics)
{
    int idx = blockIdx.x * 256 + threadIdx.x;    // 64*1024
    int bh = idx >> 10, k = idx & 1023;
    const float* pmb = pm + (((size_t)bh * 8) << 10) + k;
    const float* psb = ps + (((size_t)bh * 8) << 10) + k;
    float m = pmb[0], s = psb[0];
#pragma unroll
    for (int qt = 1; qt < 8; qt++) {
        float m2 = pmb[(size_t)qt << 10];
        float s2 = psb[(size_t)qt << 10];
        float mn = fmaxf(m, m2);
        s = s * __expf(m - mn) + s2 * __expf(m2 - mn);
        m = mn;
    }
    cm[idx] = m;
    ics[idx] = 1.0f / s;
}

// ================= fused attnout: exp-normalize + 3-term split MMA ==============
// grid (8 q-tiles, 64 bh). Per 64-wide k chunk: read w fp32, build P hi/lo in
// SMEM, load V hi/lo chunks, run (ph,vh),(ph,vl),(pl,vh).
#define AF_CM   0
#define AF_ICS  4096
#define AF_DEG  8192
#define AF_PH   8320
#define AF_PL   24704
#define AF_VH   41088
#define AF_VL   53376
#define AF_SMEM 65664

__global__ __launch_bounds__(256)
void attnout_fused(const float* __restrict__ w, const float* __restrict__ cm,
                   const float* __restrict__ ics, const __nv_bfloat16* __restrict__ vt,
                   float* __restrict__ o)
{
    extern __shared__ char smem[];
    const uint32_t sb = smem_u32(smem);
    float* cmS  = (float*)(smem + AF_CM);
    float* icsS = (float*)(smem + AF_ICS);
    int*   degS = (int*)(smem + AF_DEG);

    const int bh = blockIdx.y, b = bh >> 3, h = bh & 7;
    const int q0 = blockIdx.x << 7;
    const int tid = threadIdx.x, wid = tid >> 5, lid = tid & 31;
    const int wr = (wid & 1) << 6;
    const int wc = (wid >> 1) * 24;
    const int a_row = (lid & 7) + ((lid >> 3) & 1) * 8;
    const int a_kb  = (lid >> 4) * 8;
    const int b_row = (lid & 7);
    const int b_kb  = ((lid >> 3) & 1) * 8;

    // preload cm / ics for this bh
    for (int i = tid; i < SS; i += 256) {
        cmS[i]  = cm[bh * SS + i];
        icsS[i] = ics[bh * SS + i];
    }
    __syncthreads();
    if (tid < 16) {
        int d = 0;
        for (int j = 0; j < 64; j++)
            if (cmS[tid * 64 + j] == -1e9f) d = 1;
        degS[tid] = d;
    }
    __syncthreads();

    float acc[4][3][4];
#pragma unroll
    for (int mi = 0; mi < 4; mi++)
#pragma unroll
        for (int ni = 0; ni < 3; ni++)
#pragma unroll
            for (int r = 0; r < 4; r++) acc[mi][ni][r] = 0.f;

    const float* wb = w + (size_t)bh * SS * SS;
    const __nv_bfloat16* Vb = vt + (size_t)(b * DD + h * DKK) * 2048;

    const int pr = tid >> 2;            // 0..63 rows (and +64)
    const int pc = (tid & 3) << 2;      // float4 index base (4 per thread)

    for (int kc = 0; kc < 16; kc++) {
        bool full = (kc << 6) > q0 + 127;
        if (full && !degS[kc]) continue;

        // ---- build ph / pl chunks [128 q][64 k]
#pragma unroll
        for (int rr = 0; rr < 2; rr++) {
            int r = pr + rr * 64;
            const float* wp = wb + (size_t)(q0 + r) * SS + (kc << 6);
#pragma unroll
            for (int i = 0; i < 4; i++) {
                int c4 = pc + i;               // float4 idx 0..15
                float4 v;
                if (!full) v = *(const float4*)(wp + (c4 << 2));
                float p[4];
#pragma unroll
                for (int e = 0; e < 4; e++) {
                    int k = (kc << 6) + (c4 << 2) + e;
                    float wv = full ? 0.f : ((const float*)&v)[e];
                    if (full) p[e] = (cmS[k] == -1e9f) ? icsS[k] : 0.f;
                    else      p[e] = __expf(wv - cmS[k]) * icsS[k];
                }
                __nv_bfloat16 hh[4], ll[4];
#pragma unroll
                for (int e = 0; e < 4; e++) {
                    hh[e] = __float2bfloat16(p[e]);
                    ll[e] = __float2bfloat16(p[e] - __bfloat162float(hh[e]));
                }
                uint32_t off = SWZ128((uint32_t)((r << 7) + (c4 << 3)));
                *(uint2*)(smem + AF_PH + off) = *(uint2*)hh;
                *(uint2*)(smem + AF_PL + off) = *(uint2*)ll;
            }
        }
        // ---- load V chunks [96 n][64 k] hi & lo
#pragma unroll
        for (int t = 0; t < 3; t++) {
            int n = (tid >> 3) + t * 32;
            int c8 = tid & 7;
            uint32_t off = SWZ128((uint32_t)((n << 7) + (c8 << 4)));
            *(uint4*)(smem + AF_VH + off) =
                *(const uint4*)(Vb + (size_t)n * 2048 + (kc << 6) + (c8 << 3));
            *(uint4*)(smem + AF_VL + off) =
                *(const uint4*)(Vb + (size_t)n * 2048 + 1024 + (kc << 6) + (c8 << 3));
        }
        __syncthreads();

        // ---- 3 sub-GEMMs of BK=64
#pragma unroll
        for (int sub = 0; sub < 3; sub++) {
            const uint32_t sA = sb + ((sub < 2) ? AF_PH : AF_PL);
            const uint32_t sB = sb + ((sub == 1) ? AF_VL : AF_VH);
#pragma unroll
            for (int kk = 0; kk < 4; kk++) {
                uint32_t af[4][4], bf[3][2];
#pragma unroll
                for (int mi = 0; mi < 4; mi++) {
                    uint32_t off = (uint32_t)(((wr + mi * 16 + a_row) << 7) +
                                              ((kk * 16 + a_kb) << 1));
                    asm volatile("ldmatrix.sync.aligned.m8n8.x4.shared.b16 {%0,%1,%2,%3}, [%4];"
                                 : "=r"(af[mi][0]), "=r"(af[mi][1]), "=r"(af[mi][2]), "=r"(af[mi][3])
                                 : "r"(sA + SWZ128(off)));
                }
#pragma unroll
                for (int ni = 0; ni < 3; ni++) {
                    uint32_t off = (uint32_t)(((wc + ni * 8 + b_row) << 7) +
                                              ((kk * 16 + b_kb) << 1));
                    asm volatile("ldmatrix.sync.aligned.m8n8.x2.shared.b16 {%0,%1}, [%2];"
                                 : "=r"(bf[ni][0]), "=r"(bf[ni][1])
                                 : "r"(sB + SWZ128(off)));
                }
#pragma unroll
                for (int mi = 0; mi < 4; mi++)
#pragma unroll
                    for (int ni = 0; ni < 3; ni++) {
                        asm volatile(
                            "mma.sync.aligned.m16n8k16.row.col.f32.bf16.bf16.f32 "
                            "{%0,%1,%2,%3}, {%4,%5,%6,%7}, {%8,%9}, {%0,%1,%2,%3};"
                            : "+f"(acc[mi][ni][0]), "+f"(acc[mi][ni][1]),
                              "+f"(acc[mi][ni][2]), "+f"(acc[mi][ni][3])
                            : "r"(af[mi][0]), "r"(af[mi][1]), "r"(af[mi][2]), "r"(af[mi][3]),
                              "r"(bf[ni][0]), "r"(bf[ni][1]));
                    }
            }
        }
        __syncthreads();
    }

    const int l4 = lid >> 2, l2 = (lid & 3) << 1;
#pragma unroll
    for (int mi = 0; mi < 4; mi++) {
#pragma unroll
        for (int ni = 0; ni < 3; ni++) {
            int rg = b * SS + q0 + wr + mi * 16 + l4;
            int cg = h * DKK + wc + ni * 8 + l2;
            *(float2*)(o + (size_t)rg * DD + cg) =
                make_float2(acc[mi][ni][0], acc[mi][ni][1]);
            *(float2*)(o + (size_t)(rg + 8) * DD + cg) =
                make_float2(acc[mi][ni][2], acc[mi][ni][3]);
        }
    }
}

// ================= mask canonicalization ========================================
__global__ void detect_mask_kernel(const unsigned char* __restrict__ m)
{
    __shared__ int s_big, s_mis;
    if (threadIdx.x == 0) { s_big = 0; s_mis = 0; }
    __syncthreads();
    int big = 0, mis = 0;
    for (int i = threadIdx.x; i < NR; i += blockDim.x) {
        unsigned char v = m[i];
        if (v > 1) big = 1;
        if ((i & 3) != 0 && v != 0) mis = 1;
    }
    if (big) atomicOr(&s_big, 1);
    if (mis) atomicOr(&s_mis, 1);
    __syncthreads();
    if (threadIdx.x == 0) { g_flags[0] = s_big; g_flags[1] = s_mis; }
}

__global__ void convert_mask_kernel(const void* __restrict__ m)
{
    int i = blockIdx.x * blockDim.x + threadIdx.x;
    bool word32 = (g_flags[0] != 0) || (g_flags[1] == 0);
    unsigned char out;
    if (word32) out = (((const unsigned int*)m)[i] != 0u) ? 1 : 0;
    else        out = (((const unsigned char*)m)[i] != 0) ? 1 : 0;
    g_mask[i] = out;
}

// ================= residual add + layernorm =====================================
__global__ __launch_bounds__(256)
void addln_kernel(const float* __restrict__ a, const float* __restrict__ r,
                  const float* __restrict__ g, const float* __restrict__ beta,
                  float* __restrict__ out)
{
    const int row = blockIdx.x;
    const int tid = threadIdx.x;
    const float* ap = a + (size_t)row * DD;
    const float* rp = r + (size_t)row * DD;

    float v[3];
    float sum = 0.f, sq = 0.f;
#pragma unroll
    for (int i = 0; i < 3; i++) {
        int c = tid + (i << 8);
        v[i] = ap[c] + rp[c];
        sum += v[i];
        sq  += v[i] * v[i];
    }
#pragma unroll
    for (int off = 16; off > 0; off >>= 1) {
        sum += __shfl_xor_sync(0xffffffffu, sum, off);
        sq  += __shfl_xor_sync(0xffffffffu, sq,  off);
    }
    __shared__ float s1[8], s2[8];
    int warp = tid >> 5, lane = tid & 31;
    if (lane == 0) { s1[warp] = sum; s2[warp] = sq; }
    __syncthreads();
    if (warp == 0) {
        float aa = (lane < 8) ? s1[lane] : 0.f;
        float bb = (lane < 8) ? s2[lane] : 0.f;
#pragma unroll
        for (int off = 4; off > 0; off >>= 1) {
            aa += __shfl_xor_sync(0xffffffffu, aa, off);
            bb += __shfl_xor_sync(0xffffffffu, bb, off);
        }
        if (lane == 0) { s1[0] = aa; s2[0] = bb; }
    }
    __syncthreads();
    const float invD = 1.0f / 768.0f;
    float mean = s1[0] * invD;
    float var  = s2[0] * invD - mean * mean;
    float inv  = rsqrtf(var + 1e-5f);
#pragma unroll
    for (int i = 0; i < 3; i++) {
        int c = tid + (i << 8);
        out[(size_t)row * DD + c] = (v[i] - mean) * inv * g[c] + beta[c];
    }
}

// ================= host side ====================================================
static void run_mha(const float* xin,
                    const float* Wq, const float* bq,
                    const float* Wv, const float* bv,
                    const float* g, const float* beta,
                    __nv_bfloat16* a2, __nv_bfloat16* b2t,
                    __nv_bfloat16* qs, __nv_bfloat16* ks, __nv_bfloat16* vt,
                    float* q, float* kv, float* w,
                    float* cm, float* ics, float* pmb, float* psb,
                    float* o, float* xout)
{
    split_a_kernel<<<NR * DD / 256, 256>>>(xin, a2, DD);
    split_wt_kernel<<<dim3(DD / 32, DD / 32), dim3(32, 8)>>>(Wq, b2t, DD, DD);
    mma_gemm<false><<<dim3(DD / 128, NR / 128), 256, GEMM_SMEM_BYTES>>>(a2, b2t, bq, q, DD, 3 * DD);
    split_wt_kernel<<<dim3(DD / 32, DD / 32), dim3(32, 8)>>>(Wv, b2t, DD, DD);
    mma_gemm<false><<<dim3(DD / 128, NR / 128), 256, GEMM_SMEM_BYTES>>>(a2, b2t, bv, kv, DD, 3 * DD);

    split_qk_kernel<0><<<NR * 1024 / 256, 256>>>(q,  qs);
    split_qk_kernel<1><<<NR * 1024 / 256, 256>>>(kv, ks);
    split_vt_kernel<<<dim3(DD / 32, SS / 32, BB), dim3(32, 8)>>>(kv, vt);
    scores_mma<<<dim3(SS / 128, SS / 128, NBH), 256, GEMM_SMEM_BYTES>>>(qs, ks, w, pmb, psb);
    merge_stats<<<NBH * SS / 256, 256>>>(pmb, psb, cm, ics);
    attnout_fused<<<dim3(SS / 128, NBH), 256, AF_SMEM>>>(w, cm, ics, vt, o);
    addln_kernel<<<NR, 256>>>(o, xin, g, beta, xout);
}

extern "C" void kernel_launch(void* const* d_in, const int* in_sizes, int n_in,
                              void* d_out, int out_size)
{
    (void)in_sizes; (void)n_in; (void)out_size;

    const float* x     = (const float*)d_in[0];
    const void*  amraw = d_in[1];
    const float* a1_Wq = (const float*)d_in[2];
    const float* a1_bq = (const float*)d_in[3];
    const float* a1_Wv = (const float*)d_in[4];
    const float* a1_bv = (const float*)d_in[5];
    const float* a1_g  = (const float*)d_in[6];
    const float* a1_b  = (const float*)d_in[7];
    const float* a2_Wq = (const float*)d_in[8];
    const float* a2_bq = (const float*)d_in[9];
    const float* a2_Wv = (const float*)d_in[10];
    const float* a2_bv = (const float*)d_in[11];
    const float* a2_g  = (const float*)d_in[12];
    const float* a2_b  = (const float*)d_in[13];
    const float* f_W1  = (const float*)d_in[14];
    const float* f_b1  = (const float*)d_in[15];
    const float* f_W2  = (const float*)d_in[16];
    const float* f_b2  = (const float*)d_in[17];
    const float* f_g   = (const float*)d_in[18];
    const float* f_b   = (const float*)d_in[19];
    float* out = (float*)d_out;

    float *q, *kv, *w, *cm, *ics, *pmb, *psb, *o, *x1, *x2, *hbuf;
    __nv_bfloat16 *a2buf, *b2t, *qs, *ks, *vt;
    cudaGetSymbolAddress((void**)&q,     g_q);
    cudaGetSymbolAddress((void**)&kv,    g_kv);
    cudaGetSymbolAddress((void**)&w,     g_w);
    cudaGetSymbolAddress((void**)&cm,    g_cm);
    cudaGetSymbolAddress((void**)&ics,   g_ics);
    cudaGetSymbolAddress((void**)&pmb,   g_pm);
    cudaGetSymbolAddress((void**)&psb,   g_ps);
    cudaGetSymbolAddress((void**)&o,     g_o);
    cudaGetSymbolAddress((void**)&x1,    g_x1);
    cudaGetSymbolAddress((void**)&x2,    g_x2);
    cudaGetSymbolAddress((void**)&hbuf,  g_h);
    cudaGetSymbolAddress((void**)&a2buf, g_a2);
    cudaGetSymbolAddress((void**)&b2t,   g_b2t);
    cudaGetSymbolAddress((void**)&qs,    g_qs);
    cudaGetSymbolAddress((void**)&ks,    g_ks);
    cudaGetSymbolAddress((void**)&vt,    g_vt);

    cudaFuncSetAttribute(mma_gemm<false>, cudaFuncAttributeMaxDynamicSharedMemorySize, GEMM_SMEM_BYTES);
    cudaFuncSetAttribute(mma_gemm<true >, cudaFuncAttributeMaxDynamicSharedMemorySize, GEMM_SMEM_BYTES);
    cudaFuncSetAttribute(scores_mma,      cudaFuncAttributeMaxDynamicSharedMemorySize, GEMM_SMEM_BYTES);
    cudaFuncSetAttribute(attnout_fused,   cudaFuncAttributeMaxDynamicSharedMemorySize, AF_SMEM);

    detect_mask_kernel<<<1, 256>>>((const unsigned char*)amraw);
    convert_mask_kernel<<<NR / 256, 256>>>(amraw);

    run_mha(x,  a1_Wq, a1_bq, a1_Wv, a1_bv, a1_g, a1_b,
            a2buf, b2t, qs, ks, vt, q, kv, w, cm, ics, pmb, psb, o, x1);
    run_mha(x1, a2_Wq, a2_bq, a2_Wv, a2_bv, a2_g, a2_b,
            a2buf, b2t, qs, ks, vt, q, kv, w, cm, ics, pmb, psb, o, x2);

    split_a_kernel<<<NR * DD / 256, 256>>>(x2, a2buf, DD);
    split_wt_kernel<<<dim3(FFD / 32, DD / 32), dim3(32, 8)>>>(f_W1, b2t, DD, FFD);
    mma_gemm<true ><<<dim3(FFD / 128, NR / 128), 256, GEMM_SMEM_BYTES>>>(a2buf, b2t, f_b1, hbuf, FFD, 3 * DD);
    split_a_kernel<<<NR * FFD / 256, 256>>>(hbuf, a2buf, FFD);
    split_wt_kernel<<<dim3(DD / 32, FFD / 32), dim3(32, 8)>>>(f_W2, b2t, FFD, DD);
    mma_gemm<false><<<dim3(DD / 128, NR / 128), 256, GEMM_SMEM_BYTES>>>(a2buf, b2t, f_b2, o, DD, 3 * FFD);
    addln_kernel<<<NR, 256>>>(o, x2, f_g, f_b, out);
}